// round 8
// baseline (speedup 1.0000x reference)
#include <cuda_runtime.h>
#include <cstdint>
#include <math.h>

// Problem constants
#define Bn 4
#define Sn 2048
#define Dn 2048
#define Hn 16
#define DHn 128
#define TDn 6144            // 3*D
#define NROWS (Bn*Sn)       // 8192

// Scratch (device globals; no cudaMalloc allowed)
__device__ float g_qkv[(size_t)NROWS * TDn];   // 201 MB (tf32-formatted)
__device__ float g_y[(size_t)NROWS * Dn];      // 67 MB  (tf32-formatted)
__device__ float g_xt[(size_t)NROWS * Dn];     // 67 MB  x  pre-converted
__device__ float g_wq[(size_t)TDn * Dn];       // 50 MB  qkv_w pre-converted
__device__ float g_wo[(size_t)Dn * Dn];        // 17 MB  out_w pre-converted

__device__ __forceinline__ uint32_t f2tf32(float x) {
    uint32_t r;
    asm("cvt.rna.tf32.f32 %0, %1;" : "=r"(r) : "f"(x));
    return r;
}

__device__ __forceinline__ void mma_tf32(float* d,
                                         uint32_t a0, uint32_t a1,
                                         uint32_t a2, uint32_t a3,
                                         uint32_t b0, uint32_t b1) {
    asm volatile(
        "mma.sync.aligned.m16n8k8.row.col.f32.tf32.tf32.f32 "
        "{%0,%1,%2,%3}, {%4,%5,%6,%7}, {%8,%9}, {%0,%1,%2,%3};"
        : "+f"(d[0]), "+f"(d[1]), "+f"(d[2]), "+f"(d[3])
        : "r"(a0), "r"(a1), "r"(a2), "r"(a3), "r"(b0), "r"(b1));
}

__device__ __forceinline__ void cp16(void* smem_ptr, const void* gptr) {
    uint32_t sa = (uint32_t)__cvta_generic_to_shared(smem_ptr);
    asm volatile("cp.async.cg.shared.global [%0], [%1], 16;"
                 :: "r"(sa), "l"(gptr));
}
#define CP_COMMIT() asm volatile("cp.async.commit_group;" ::: "memory")
#define CP_WAIT(n)  asm volatile("cp.async.wait_group %0;" :: "n"(n) : "memory")

// ---------------------------------------------------------------------------
// Pre-convert fp32 -> tf32-formatted fp32 (vectorized)
// ---------------------------------------------------------------------------
__global__ __launch_bounds__(256) void conv_tf32_kernel(
    const float* __restrict__ in, float* __restrict__ out, int n4)
{
    int i = blockIdx.x * blockDim.x + threadIdx.x;
    if (i >= n4) return;
    float4 v = ((const float4*)in)[i];
    uint4 u = make_uint4(f2tf32(v.x), f2tf32(v.y), f2tf32(v.z), f2tf32(v.w));
    ((uint4*)out)[i] = u;
}

// ---------------------------------------------------------------------------
// cp.async tf32 GEMM: C[M,N] = A[M,K] @ W[N,K]^T + bias[N]
// qkv_mode: fused RoPE on q,k cols + tf32-round ALL outputs.
// CTA 128x128, 128 threads = 4 warps (2m x 2n), warp tile 64x64.
// ---------------------------------------------------------------------------
#define KC2 16
#define STG 4
#define STR2 20
#define ATILE (128 * STR2)
#define STAGE_F (2 * ATILE)
#define GEMM2_SMEM (STG * STAGE_F * 4)        // 81920 bytes

__global__ void __launch_bounds__(128, 2) mma_gemm_ca(
    const float* __restrict__ A, const float* __restrict__ W,
    const float* __restrict__ bias, float* __restrict__ C,
    int M, int N, int K, int qkv_mode)
{
    extern __shared__ float sm[];
    const int tid = threadIdx.x;
    const int wid = tid >> 5;
    const int lid = tid & 31;
    const int g   = lid >> 2;
    const int tg  = lid & 3;
    const int wm  = wid >> 1;
    const int wn  = wid & 1;
    const int m0 = blockIdx.y << 7;
    const int n0 = blockIdx.x << 7;

    const float* Abase = A + (size_t)m0 * K;
    const float* Wbase = W + (size_t)n0 * K;

    float acc[4][8][4];
#pragma unroll
    for (int mi = 0; mi < 4; mi++)
#pragma unroll
        for (int ni = 0; ni < 8; ni++)
#pragma unroll
            for (int r = 0; r < 4; r++) acc[mi][ni][r] = 0.f;

    const int nc = K / KC2;

    auto issue_load = [&](int stage, int chunk) {
        const int k0 = chunk * KC2;
        float* As = sm + stage * STAGE_F;
        float* Bs = As + ATILE;
#pragma unroll
        for (int i = 0; i < 4; i++) {
            const int idx = i * 128 + tid;
            const int row = idx >> 2;
            const int c4  = (idx & 3) << 2;
            cp16(&As[row * STR2 + c4], Abase + (size_t)row * K + k0 + c4);
            cp16(&Bs[row * STR2 + c4], Wbase + (size_t)row * K + k0 + c4);
        }
    };

    auto compute = [&](int stage) {
        const float* As = sm + stage * STAGE_F;
        const float* Bs = As + ATILE;
#pragma unroll
        for (int ks = 0; ks < 2; ks++) {
            const int kc = ks * 8;
            uint32_t bf[8][2];
#pragma unroll
            for (int ni = 0; ni < 8; ni++) {
                const float* bp = &Bs[(wn * 64 + ni * 8 + g) * STR2 + kc + tg];
                bf[ni][0] = __float_as_uint(bp[0]);
                bf[ni][1] = __float_as_uint(bp[4]);
            }
#pragma unroll
            for (int mi = 0; mi < 4; mi++) {
                const float* ap = &As[(wm * 64 + mi * 16 + g) * STR2 + kc + tg];
                uint32_t a0 = __float_as_uint(ap[0]);
                uint32_t a1 = __float_as_uint(ap[8 * STR2]);
                uint32_t a2 = __float_as_uint(ap[4]);
                uint32_t a3 = __float_as_uint(ap[8 * STR2 + 4]);
#pragma unroll
                for (int ni = 0; ni < 8; ni++)
                    mma_tf32(acc[mi][ni], a0, a1, a2, a3,
                             bf[ni][0], bf[ni][1]);
            }
        }
    };

#pragma unroll
    for (int s = 0; s < STG - 1; s++) {
        issue_load(s, s);
        CP_COMMIT();
    }

    for (int c = 0; c < nc; c++) {
        CP_WAIT(STG - 2);
        __syncthreads();
        const int nxt = c + STG - 1;
        if (nxt < nc) issue_load(nxt & (STG - 1), nxt);
        CP_COMMIT();
        compute(c & (STG - 1));
    }

    // epilogue: bias (+ RoPE on q,k cols), tf32-round in qkv mode, store
    const bool do_rope = qkv_mode && (n0 < 2 * Dn);
#pragma unroll
    for (int ni = 0; ni < 8; ni++) {
        const int col = n0 + wn * 64 + ni * 8 + 2 * tg;
        const float2 bj = *(const float2*)&bias[col];
        float freq = 0.f;
        if (do_rope) {
            const int d2 = (col & 127) >> 1;
            freq = powf(10000.0f, -(float)d2 / 64.0f);
        }
#pragma unroll
        for (int mi = 0; mi < 4; mi++) {
            const int row = m0 + wm * 64 + mi * 16 + g;
            float2 o0, o1;
            o0.x = acc[mi][ni][0] + bj.x;
            o0.y = acc[mi][ni][1] + bj.y;
            o1.x = acc[mi][ni][2] + bj.x;
            o1.y = acc[mi][ni][3] + bj.y;
            if (do_rope) {
                float sn, cs;
                float omega = (float)(row & (Sn - 1)) * freq;
                sincosf(omega, &sn, &cs);
                float r0x = o0.x * cs - o0.y * sn;
                float r0y = o0.x * sn + o0.y * cs;
                o0.x = r0x; o0.y = r0y;
                omega = (float)((row + 8) & (Sn - 1)) * freq;
                sincosf(omega, &sn, &cs);
                float r1x = o1.x * cs - o1.y * sn;
                float r1y = o1.x * sn + o1.y * cs;
                o1.x = r1x; o1.y = r1y;
            }
            if (qkv_mode) {
                o0.x = __uint_as_float(f2tf32(o0.x));
                o0.y = __uint_as_float(f2tf32(o0.y));
                o1.x = __uint_as_float(f2tf32(o1.x));
                o1.y = __uint_as_float(f2tf32(o1.y));
            }
            *(float2*)&C[(size_t)row * N + col] = o0;
            *(float2*)&C[(size_t)(row + 8) * N + col] = o1;
        }
    }
}

// ---------------------------------------------------------------------------
// Tensor-core flash attention (causal), tf32 mma, cp.async K/V double-buffer.
// Requires qkv already tf32-formatted.
// ---------------------------------------------------------------------------
#define KSTR 132
#define VSTR 136
#define PSTRW 132
#define FA_SMEM ((2 * 64 * KSTR + 2 * 64 * VSTR + 128 * PSTRW) * 4)  // 204800

__global__ __launch_bounds__(256) void flash_attn_tc(
    const float* __restrict__ qkv, float* __restrict__ Y)
{
    extern __shared__ float sm[];
    float* Ksb[2] = { sm, sm + 64 * KSTR };
    float* Vsb[2] = { sm + 2 * 64 * KSTR, sm + 2 * 64 * KSTR + 64 * VSTR };
    float* Pw = sm + 2 * 64 * KSTR + 2 * 64 * VSTR;

    const int tid = threadIdx.x;
    const int wid = tid >> 5;
    const int lid = tid & 31;
    const int g   = lid >> 2;
    const int tg  = lid & 3;
    const int qb  = blockIdx.x;
    const int q0  = qb * 128;
    const int bh  = blockIdx.y;
    const int b   = bh >> 4;
    const int h   = bh & 15;

    const int row0 = q0 + wid * 16 + g;
    const float scale = 0.08838834764831845f;

    const float* kbase = qkv + ((size_t)(b * Sn)) * TDn + Dn + h * DHn;
    const float* vbase = kbase + Dn;

    auto issue_kv = [&](int stage, int kb) {
        const int k0 = kb * 64;
        float* Ks = Ksb[stage];
        float* Vs = Vsb[stage];
#pragma unroll
        for (int i = 0; i < 8; i++) {
            int idx = tid + i * 256;
            int r  = idx >> 5;
            int c4 = (idx & 31) << 2;
            const size_t go = (size_t)(k0 + r) * TDn + c4;
            cp16(&Ks[r * KSTR + c4], kbase + go);
            cp16(&Vs[r * VSTR + c4], vbase + go);
        }
    };

    // Q fragments (scaled, tf32)
    const float* qptr = qkv + ((size_t)(b * Sn + row0)) * TDn + h * DHn;
    uint32_t qf[16][4];
#pragma unroll
    for (int kt = 0; kt < 16; kt++) {
        qf[kt][0] = f2tf32(qptr[kt * 8 + tg] * scale);
        qf[kt][1] = f2tf32(qptr[(size_t)8 * TDn + kt * 8 + tg] * scale);
        qf[kt][2] = f2tf32(qptr[kt * 8 + tg + 4] * scale);
        qf[kt][3] = f2tf32(qptr[(size_t)8 * TDn + kt * 8 + tg + 4] * scale);
    }

    float ofr[16][4];
#pragma unroll
    for (int nt = 0; nt < 16; nt++)
#pragma unroll
        for (int r = 0; r < 4; r++) ofr[nt][r] = 0.f;

    float m0 = -1e30f, m1 = -1e30f, l0 = 0.f, l1 = 0.f;
    float* prow = Pw + (wid * 16) * PSTRW;

    const int nkb = 2 * qb + 2;
    issue_kv(0, 0);
    CP_COMMIT();

    for (int kb = 0; kb < nkb; kb++) {
        __syncthreads();   // prior compute done -> safe to overwrite other buf
        if (kb + 1 < nkb) { issue_kv((kb + 1) & 1, kb + 1); CP_COMMIT(); }
        if (kb + 1 < nkb) { CP_WAIT(1); } else { CP_WAIT(0); }
        __syncthreads();   // tile kb visible to all threads

        const float* Ks = Ksb[kb & 1];
        const float* Vs = Vsb[kb & 1];
        const int k0 = kb * 64;

        float sc[8][4];
#pragma unroll
        for (int nt = 0; nt < 8; nt++)
#pragma unroll
            for (int r = 0; r < 4; r++) sc[nt][r] = 0.f;

#pragma unroll
        for (int kt = 0; kt < 16; kt++) {
#pragma unroll
            for (int nt = 0; nt < 8; nt++) {
                const float* bp = &Ks[(nt * 8 + g) * KSTR + kt * 8 + tg];
                uint32_t b0 = __float_as_uint(bp[0]);
                uint32_t b1 = __float_as_uint(bp[4]);
                mma_tf32(sc[nt], qf[kt][0], qf[kt][1], qf[kt][2], qf[kt][3],
                         b0, b1);
            }
        }

        if (kb >= 2 * qb) {
#pragma unroll
            for (int nt = 0; nt < 8; nt++) {
                int col = k0 + nt * 8 + 2 * tg;
                if (col > row0)     sc[nt][0] = -1e30f;
                if (col + 1 > row0) sc[nt][1] = -1e30f;
                if (col > row0 + 8)     sc[nt][2] = -1e30f;
                if (col + 1 > row0 + 8) sc[nt][3] = -1e30f;
            }
        }

        float mx0 = -1e30f, mx1 = -1e30f;
#pragma unroll
        for (int nt = 0; nt < 8; nt++) {
            mx0 = fmaxf(mx0, fmaxf(sc[nt][0], sc[nt][1]));
            mx1 = fmaxf(mx1, fmaxf(sc[nt][2], sc[nt][3]));
        }
        mx0 = fmaxf(mx0, __shfl_xor_sync(0xffffffffu, mx0, 1));
        mx0 = fmaxf(mx0, __shfl_xor_sync(0xffffffffu, mx0, 2));
        mx1 = fmaxf(mx1, __shfl_xor_sync(0xffffffffu, mx1, 1));
        mx1 = fmaxf(mx1, __shfl_xor_sync(0xffffffffu, mx1, 2));

        const float mn0 = fmaxf(m0, mx0);
        const float mn1 = fmaxf(m1, mx1);
        const float a0 = __expf(m0 - mn0);
        const float a1 = __expf(m1 - mn1);
        m0 = mn0; m1 = mn1;

        float s0 = 0.f, s1 = 0.f;
#pragma unroll
        for (int nt = 0; nt < 8; nt++) {
            sc[nt][0] = __expf(sc[nt][0] - mn0);
            sc[nt][1] = __expf(sc[nt][1] - mn0);
            sc[nt][2] = __expf(sc[nt][2] - mn1);
            sc[nt][3] = __expf(sc[nt][3] - mn1);
            s0 += sc[nt][0] + sc[nt][1];
            s1 += sc[nt][2] + sc[nt][3];
        }
        s0 += __shfl_xor_sync(0xffffffffu, s0, 1);
        s0 += __shfl_xor_sync(0xffffffffu, s0, 2);
        s1 += __shfl_xor_sync(0xffffffffu, s1, 1);
        s1 += __shfl_xor_sync(0xffffffffu, s1, 2);
        l0 = l0 * a0 + s0;
        l1 = l1 * a1 + s1;

#pragma unroll
        for (int nt = 0; nt < 16; nt++) {
            ofr[nt][0] *= a0; ofr[nt][1] *= a0;
            ofr[nt][2] *= a1; ofr[nt][3] *= a1;
        }

        __syncwarp();
#pragma unroll
        for (int nt = 0; nt < 8; nt++) {
            const int col = nt * 8 + 2 * tg;
            prow[g * PSTRW + col]           = __uint_as_float(f2tf32(sc[nt][0]));
            prow[g * PSTRW + col + 1]       = __uint_as_float(f2tf32(sc[nt][1]));
            prow[(g + 8) * PSTRW + col]     = __uint_as_float(f2tf32(sc[nt][2]));
            prow[(g + 8) * PSTRW + col + 1] = __uint_as_float(f2tf32(sc[nt][3]));
        }
        __syncwarp();

#pragma unroll
        for (int kt = 0; kt < 8; kt++) {
            uint32_t pa0 = __float_as_uint(prow[g * PSTRW + kt * 8 + tg]);
            uint32_t pa1 = __float_as_uint(prow[(g + 8) * PSTRW + kt * 8 + tg]);
            uint32_t pa2 = __float_as_uint(prow[g * PSTRW + kt * 8 + tg + 4]);
            uint32_t pa3 = __float_as_uint(prow[(g + 8) * PSTRW + kt * 8 + tg + 4]);
#pragma unroll
            for (int nt = 0; nt < 16; nt++) {
                uint32_t b0 = __float_as_uint(Vs[(kt * 8 + tg) * VSTR + nt * 8 + g]);
                uint32_t b1 = __float_as_uint(Vs[(kt * 8 + tg + 4) * VSTR + nt * 8 + g]);
                mma_tf32(ofr[nt], pa0, pa1, pa2, pa3, b0, b1);
            }
        }
    }

    const float inv0 = 1.0f / l0;
    const float inv1 = 1.0f / l1;
    float* yrow = Y + ((size_t)(b * Sn + row0)) * Dn + h * DHn;
#pragma unroll
    for (int nt = 0; nt < 16; nt++) {
        const int col = nt * 8 + 2 * tg;
        float2 o0, o1;
        o0.x = __uint_as_float(f2tf32(ofr[nt][0] * inv0));
        o0.y = __uint_as_float(f2tf32(ofr[nt][1] * inv0));
        o1.x = __uint_as_float(f2tf32(ofr[nt][2] * inv1));
        o1.y = __uint_as_float(f2tf32(ofr[nt][3] * inv1));
        *(float2*)&yrow[col] = o0;
        *(float2*)&yrow[(size_t)8 * Dn + col] = o1;
    }
}

// ---------------------------------------------------------------------------
extern "C" void kernel_launch(void* const* d_in, const int* in_sizes, int n_in,
                              void* d_out, int out_size)
{
    (void)in_sizes; (void)n_in; (void)out_size;
    const float* x      = (const float*)d_in[0];
    const float* qkv_w  = (const float*)d_in[1];
    const float* qkv_b  = (const float*)d_in[2];
    const float* out_w  = (const float*)d_in[3];
    const float* out_b  = (const float*)d_in[4];
    float* out = (float*)d_out;

    float *qkv, *y, *xt, *wq, *wo;
    cudaGetSymbolAddress((void**)&qkv, g_qkv);
    cudaGetSymbolAddress((void**)&y, g_y);
    cudaGetSymbolAddress((void**)&xt, g_xt);
    cudaGetSymbolAddress((void**)&wq, g_wq);
    cudaGetSymbolAddress((void**)&wo, g_wo);

    cudaFuncSetAttribute(mma_gemm_ca,
                         cudaFuncAttributeMaxDynamicSharedMemorySize, GEMM2_SMEM);
    cudaFuncSetAttribute(flash_attn_tc,
                         cudaFuncAttributeMaxDynamicSharedMemorySize, FA_SMEM);

    // 0) Pre-convert inputs to tf32 format
    {
        int n4x = (NROWS * Dn) / 4;
        conv_tf32_kernel<<<(n4x + 255) / 256, 256>>>(x, xt, n4x);
        int n4q = (TDn * Dn) / 4;
        conv_tf32_kernel<<<(n4q + 255) / 256, 256>>>(qkv_w, wq, n4q);
        int n4o = (Dn * Dn) / 4;
        conv_tf32_kernel<<<(n4o + 255) / 256, 256>>>(out_w, wo, n4o);
    }

    // 1) QKV projection + fused RoPE, tf32-rounded outputs
    {
        dim3 grid(TDn / 128, NROWS / 128);
        mma_gemm_ca<<<grid, 128, GEMM2_SMEM>>>(xt, wq, qkv_b, qkv,
                                               NROWS, TDn, Dn, 1);
    }

    // 2) Flash attention (tensor-core tf32, cp.async pipelined K/V)
    {
        dim3 grid(Sn / 128, Bn * Hn);
        flash_attn_tc<<<grid, 256, FA_SMEM>>>(qkv, y);
    }

    // 3) Output projection
    {
        dim3 grid(Dn / 128, NROWS / 128);
        mma_gemm_ca<<<grid, 128, GEMM2_SMEM>>>(y, wo, out_b, out,
                                               NROWS, Dn, Dn, 0);
    }
}

// round 10
// speedup vs baseline: 1.6181x; 1.6181x over previous
#include <cuda_runtime.h>
#include <cuda_fp16.h>
#include <cstdint>
#include <math.h>

// Problem constants
#define Bn 4
#define Sn 2048
#define Dn 2048
#define Hn 16
#define DHn 128
#define TDn 6144            // 3*D
#define NROWS (Bn*Sn)       // 8192

// Scratch (device globals; no cudaMalloc allowed)
__device__ float  g_qkv[(size_t)NROWS * TDn];   // 201 MB fp32 (RoPE'd)
__device__ __half g_y[(size_t)NROWS * Dn];      // 33 MB  half (attn out)
__device__ __half g_xt[(size_t)NROWS * Dn];     // 33 MB  x  half
__device__ __half g_wq[(size_t)TDn * Dn];       // 25 MB  qkv_w half
__device__ __half g_wo[(size_t)Dn * Dn];        // 8 MB   out_w half

__device__ __forceinline__ uint32_t f2tf32(float x) {
    uint32_t r;
    asm("cvt.rna.tf32.f32 %0, %1;" : "=r"(r) : "f"(x));
    return r;
}

__device__ __forceinline__ void mma_tf32(float* d,
                                         uint32_t a0, uint32_t a1,
                                         uint32_t a2, uint32_t a3,
                                         uint32_t b0, uint32_t b1) {
    asm volatile(
        "mma.sync.aligned.m16n8k8.row.col.f32.tf32.tf32.f32 "
        "{%0,%1,%2,%3}, {%4,%5,%6,%7}, {%8,%9}, {%0,%1,%2,%3};"
        : "+f"(d[0]), "+f"(d[1]), "+f"(d[2]), "+f"(d[3])
        : "r"(a0), "r"(a1), "r"(a2), "r"(a3), "r"(b0), "r"(b1));
}

__device__ __forceinline__ void mma_f16(float* d,
                                        uint32_t a0, uint32_t a1,
                                        uint32_t a2, uint32_t a3,
                                        uint32_t b0, uint32_t b1) {
    asm volatile(
        "mma.sync.aligned.m16n8k16.row.col.f32.f16.f16.f32 "
        "{%0,%1,%2,%3}, {%4,%5,%6,%7}, {%8,%9}, {%0,%1,%2,%3};"
        : "+f"(d[0]), "+f"(d[1]), "+f"(d[2]), "+f"(d[3])
        : "r"(a0), "r"(a1), "r"(a2), "r"(a3), "r"(b0), "r"(b1));
}

__device__ __forceinline__ void cp16(void* smem_ptr, const void* gptr) {
    uint32_t sa = (uint32_t)__cvta_generic_to_shared(smem_ptr);
    asm volatile("cp.async.cg.shared.global [%0], [%1], 16;"
                 :: "r"(sa), "l"(gptr));
}
#define CP_COMMIT() asm volatile("cp.async.commit_group;" ::: "memory")
#define CP_WAIT(n)  asm volatile("cp.async.wait_group %0;" :: "n"(n) : "memory")

// ---------------------------------------------------------------------------
// Pre-convert fp32 -> fp16 (8 elems/thread)
// ---------------------------------------------------------------------------
__global__ __launch_bounds__(256) void conv_h_kernel(
    const float* __restrict__ in, __half* __restrict__ out, int n8)
{
    int i = blockIdx.x * blockDim.x + threadIdx.x;
    if (i >= n8) return;
    float4 v0 = ((const float4*)in)[2 * i];
    float4 v1 = ((const float4*)in)[2 * i + 1];
    __half2 h0 = __floats2half2_rn(v0.x, v0.y);
    __half2 h1 = __floats2half2_rn(v0.z, v0.w);
    __half2 h2 = __floats2half2_rn(v1.x, v1.y);
    __half2 h3 = __floats2half2_rn(v1.z, v1.w);
    uint4 u;
    u.x = *(uint32_t*)&h0; u.y = *(uint32_t*)&h1;
    u.z = *(uint32_t*)&h2; u.w = *(uint32_t*)&h3;
    ((uint4*)out)[i] = u;
}

// ---------------------------------------------------------------------------
// fp16 mma GEMM: C[M,N] = A[M,K] @ W[N,K]^T + bias[N]  (A,W half; C float)
// qkv_mode: fused RoPE on q,k columns.
// CTA 128x128, 128 threads = 4 warps (2m x 2n), warp tile 64x64.
// KC=32 halves, 4 stages, stride-40-half smem (conflict-free). 2 CTAs/SM.
// ---------------------------------------------------------------------------
#define KC2 32
#define STG 4
#define STRH 40                               // halves per row
#define ATILE_H (128 * STRH)                  // 5120 halves (10240B)
#define STAGE_H (2 * ATILE_H)
#define GEMM2_SMEM (STG * STAGE_H * 2)        // 81920 bytes

__global__ void __launch_bounds__(128, 2) mma_gemm_h(
    const __half* __restrict__ A, const __half* __restrict__ W,
    const float* __restrict__ bias, float* __restrict__ C,
    int M, int N, int K, int qkv_mode)
{
    extern __shared__ __half smh[];
    const int tid = threadIdx.x;
    const int wid = tid >> 5;
    const int lid = tid & 31;
    const int g   = lid >> 2;
    const int tg  = lid & 3;
    const int wm  = wid >> 1;
    const int wn  = wid & 1;
    const int m0 = blockIdx.y << 7;
    const int n0 = blockIdx.x << 7;

    const __half* Abase = A + (size_t)m0 * K;
    const __half* Wbase = W + (size_t)n0 * K;

    float acc[4][8][4];
#pragma unroll
    for (int mi = 0; mi < 4; mi++)
#pragma unroll
        for (int ni = 0; ni < 8; ni++)
#pragma unroll
            for (int r = 0; r < 4; r++) acc[mi][ni][r] = 0.f;

    const int nc = K / KC2;

    auto issue_load = [&](int stage, int chunk) {
        const int k0 = chunk * KC2;
        __half* As = smh + stage * STAGE_H;
        __half* Bs = As + ATILE_H;
#pragma unroll
        for (int i = 0; i < 4; i++) {
            const int idx = i * 128 + tid;
            const int row = idx >> 2;            // 0..127
            const int s8  = (idx & 3) << 3;      // 0,8,16,24 halves
            cp16(&As[row * STRH + s8], Abase + (size_t)row * K + k0 + s8);
            cp16(&Bs[row * STRH + s8], Wbase + (size_t)row * K + k0 + s8);
        }
    };

    auto compute = [&](int stage) {
        const __half* As = smh + stage * STAGE_H;
        const __half* Bs = As + ATILE_H;
#pragma unroll
        for (int ks = 0; ks < 2; ks++) {
            const int kc = ks * 16;
            uint32_t bf[8][2];
#pragma unroll
            for (int ni = 0; ni < 8; ni++) {
                const __half* bp = &Bs[(wn * 64 + ni * 8 + g) * STRH + kc + 2 * tg];
                bf[ni][0] = *(const uint32_t*)bp;
                bf[ni][1] = *(const uint32_t*)(bp + 8);
            }
#pragma unroll
            for (int mi = 0; mi < 4; mi++) {
                const __half* ap = &As[(wm * 64 + mi * 16 + g) * STRH + kc + 2 * tg];
                uint32_t a0 = *(const uint32_t*)ap;
                uint32_t a1 = *(const uint32_t*)(ap + 8 * STRH);
                uint32_t a2 = *(const uint32_t*)(ap + 8);
                uint32_t a3 = *(const uint32_t*)(ap + 8 * STRH + 8);
#pragma unroll
                for (int ni = 0; ni < 8; ni++)
                    mma_f16(acc[mi][ni], a0, a1, a2, a3,
                            bf[ni][0], bf[ni][1]);
            }
        }
    };

#pragma unroll
    for (int s = 0; s < STG - 1; s++) {
        issue_load(s, s);
        CP_COMMIT();
    }

    for (int c = 0; c < nc; c++) {
        CP_WAIT(STG - 2);
        __syncthreads();
        const int nxt = c + STG - 1;
        if (nxt < nc) issue_load(nxt & (STG - 1), nxt);
        CP_COMMIT();
        compute(c & (STG - 1));
    }

    // epilogue: bias (+ RoPE on q,k cols), store fp32
    const bool do_rope = qkv_mode && (n0 < 2 * Dn);
#pragma unroll
    for (int ni = 0; ni < 8; ni++) {
        const int col = n0 + wn * 64 + ni * 8 + 2 * tg;
        const float2 bj = *(const float2*)&bias[col];
        float freq = 0.f;
        if (do_rope) {
            const int d2 = (col & 127) >> 1;
            freq = powf(10000.0f, -(float)d2 / 64.0f);
        }
#pragma unroll
        for (int mi = 0; mi < 4; mi++) {
            const int row = m0 + wm * 64 + mi * 16 + g;
            float2 o0, o1;
            o0.x = acc[mi][ni][0] + bj.x;
            o0.y = acc[mi][ni][1] + bj.y;
            o1.x = acc[mi][ni][2] + bj.x;
            o1.y = acc[mi][ni][3] + bj.y;
            if (do_rope) {
                float sn, cs;
                float omega = (float)(row & (Sn - 1)) * freq;
                sincosf(omega, &sn, &cs);
                float r0x = o0.x * cs - o0.y * sn;
                float r0y = o0.x * sn + o0.y * cs;
                o0.x = r0x; o0.y = r0y;
                omega = (float)((row + 8) & (Sn - 1)) * freq;
                sincosf(omega, &sn, &cs);
                float r1x = o1.x * cs - o1.y * sn;
                float r1y = o1.x * sn + o1.y * cs;
                o1.x = r1x; o1.y = r1y;
            }
            *(float2*)&C[(size_t)row * N + col] = o0;
            *(float2*)&C[(size_t)(row + 8) * N + col] = o1;
        }
    }
}

// ---------------------------------------------------------------------------
// Tensor-core flash attention (causal), tf32 mma. (R7-proven; half output)
// ---------------------------------------------------------------------------
#define KSTR 132
#define VSTR 136
#define PSTRW 132
#define FA_SMEM ((64 * KSTR + 64 * VSTR + 128 * PSTRW) * 4)

__global__ __launch_bounds__(256) void flash_attn_tc(
    const float* __restrict__ qkv, __half* __restrict__ Y)
{
    extern __shared__ float sm[];
    float* Ks = sm;
    float* Vs = Ks + 64 * KSTR;
    float* Pw = Vs + 64 * VSTR;

    const int tid = threadIdx.x;
    const int wid = tid >> 5;
    const int lid = tid & 31;
    const int g   = lid >> 2;
    const int tg  = lid & 3;
    const int qb  = blockIdx.x;
    const int q0  = qb * 128;
    const int bh  = blockIdx.y;
    const int b   = bh >> 4;
    const int h   = bh & 15;

    const int row0 = q0 + wid * 16 + g;
    const float scale = 0.08838834764831845f;

    const float* qptr = qkv + ((size_t)(b * Sn + row0)) * TDn + h * DHn;
    uint32_t qf[16][4];
#pragma unroll
    for (int kt = 0; kt < 16; kt++) {
        qf[kt][0] = f2tf32(qptr[kt * 8 + tg] * scale);
        qf[kt][1] = f2tf32(qptr[(size_t)8 * TDn + kt * 8 + tg] * scale);
        qf[kt][2] = f2tf32(qptr[kt * 8 + tg + 4] * scale);
        qf[kt][3] = f2tf32(qptr[(size_t)8 * TDn + kt * 8 + tg + 4] * scale);
    }

    float ofr[16][4];
#pragma unroll
    for (int nt = 0; nt < 16; nt++)
#pragma unroll
        for (int r = 0; r < 4; r++) ofr[nt][r] = 0.f;

    float m0 = -1e30f, m1 = -1e30f, l0 = 0.f, l1 = 0.f;

    const float* kbase = qkv + ((size_t)(b * Sn)) * TDn + Dn + h * DHn;
    const float* vbase = kbase + Dn;
    float* prow = Pw + (wid * 16) * PSTRW;

    const int nkb = 2 * qb + 2;
    for (int kb = 0; kb < nkb; kb++) {
        __syncthreads();
        const int k0 = kb * 64;

#pragma unroll
        for (int i = 0; i < 8; i++) {
            int idx = tid + i * 256;
            int r  = idx >> 5;
            int c4 = (idx & 31) << 2;
            const size_t go = (size_t)(k0 + r) * TDn + c4;
            float4 kv = *(const float4*)(kbase + go);
            uint4 ku = make_uint4(f2tf32(kv.x), f2tf32(kv.y),
                                  f2tf32(kv.z), f2tf32(kv.w));
            *(uint4*)&Ks[r * KSTR + c4] = ku;
            float4 vv = *(const float4*)(vbase + go);
            uint4 vu = make_uint4(f2tf32(vv.x), f2tf32(vv.y),
                                  f2tf32(vv.z), f2tf32(vv.w));
            *(uint4*)&Vs[r * VSTR + c4] = vu;
        }
        __syncthreads();

        float sc[8][4];
#pragma unroll
        for (int nt = 0; nt < 8; nt++)
#pragma unroll
            for (int r = 0; r < 4; r++) sc[nt][r] = 0.f;

#pragma unroll
        for (int kt = 0; kt < 16; kt++) {
#pragma unroll
            for (int nt = 0; nt < 8; nt++) {
                const float* bp = &Ks[(nt * 8 + g) * KSTR + kt * 8 + tg];
                uint32_t b0 = __float_as_uint(bp[0]);
                uint32_t b1 = __float_as_uint(bp[4]);
                mma_tf32(sc[nt], qf[kt][0], qf[kt][1], qf[kt][2], qf[kt][3],
                         b0, b1);
            }
        }

        if (kb >= 2 * qb) {
#pragma unroll
            for (int nt = 0; nt < 8; nt++) {
                int col = k0 + nt * 8 + 2 * tg;
                if (col > row0)     sc[nt][0] = -1e30f;
                if (col + 1 > row0) sc[nt][1] = -1e30f;
                if (col > row0 + 8)     sc[nt][2] = -1e30f;
                if (col + 1 > row0 + 8) sc[nt][3] = -1e30f;
            }
        }

        float mx0 = -1e30f, mx1 = -1e30f;
#pragma unroll
        for (int nt = 0; nt < 8; nt++) {
            mx0 = fmaxf(mx0, fmaxf(sc[nt][0], sc[nt][1]));
            mx1 = fmaxf(mx1, fmaxf(sc[nt][2], sc[nt][3]));
        }
        mx0 = fmaxf(mx0, __shfl_xor_sync(0xffffffffu, mx0, 1));
        mx0 = fmaxf(mx0, __shfl_xor_sync(0xffffffffu, mx0, 2));
        mx1 = fmaxf(mx1, __shfl_xor_sync(0xffffffffu, mx1, 1));
        mx1 = fmaxf(mx1, __shfl_xor_sync(0xffffffffu, mx1, 2));

        const float mn0 = fmaxf(m0, mx0);
        const float mn1 = fmaxf(m1, mx1);
        const float a0 = __expf(m0 - mn0);
        const float a1 = __expf(m1 - mn1);
        m0 = mn0; m1 = mn1;

        float s0 = 0.f, s1 = 0.f;
#pragma unroll
        for (int nt = 0; nt < 8; nt++) {
            sc[nt][0] = __expf(sc[nt][0] - mn0);
            sc[nt][1] = __expf(sc[nt][1] - mn0);
            sc[nt][2] = __expf(sc[nt][2] - mn1);
            sc[nt][3] = __expf(sc[nt][3] - mn1);
            s0 += sc[nt][0] + sc[nt][1];
            s1 += sc[nt][2] + sc[nt][3];
        }
        s0 += __shfl_xor_sync(0xffffffffu, s0, 1);
        s0 += __shfl_xor_sync(0xffffffffu, s0, 2);
        s1 += __shfl_xor_sync(0xffffffffu, s1, 1);
        s1 += __shfl_xor_sync(0xffffffffu, s1, 2);
        l0 = l0 * a0 + s0;
        l1 = l1 * a1 + s1;

#pragma unroll
        for (int nt = 0; nt < 16; nt++) {
            ofr[nt][0] *= a0; ofr[nt][1] *= a0;
            ofr[nt][2] *= a1; ofr[nt][3] *= a1;
        }

        __syncwarp();
#pragma unroll
        for (int nt = 0; nt < 8; nt++) {
            const int col = nt * 8 + 2 * tg;
            prow[g * PSTRW + col]           = __uint_as_float(f2tf32(sc[nt][0]));
            prow[g * PSTRW + col + 1]       = __uint_as_float(f2tf32(sc[nt][1]));
            prow[(g + 8) * PSTRW + col]     = __uint_as_float(f2tf32(sc[nt][2]));
            prow[(g + 8) * PSTRW + col + 1] = __uint_as_float(f2tf32(sc[nt][3]));
        }
        __syncwarp();

#pragma unroll
        for (int kt = 0; kt < 8; kt++) {
            uint32_t pa0 = __float_as_uint(prow[g * PSTRW + kt * 8 + tg]);
            uint32_t pa1 = __float_as_uint(prow[(g + 8) * PSTRW + kt * 8 + tg]);
            uint32_t pa2 = __float_as_uint(prow[g * PSTRW + kt * 8 + tg + 4]);
            uint32_t pa3 = __float_as_uint(prow[(g + 8) * PSTRW + kt * 8 + tg + 4]);
#pragma unroll
            for (int nt = 0; nt < 16; nt++) {
                uint32_t b0 = __float_as_uint(Vs[(kt * 8 + tg) * VSTR + nt * 8 + g]);
                uint32_t b1 = __float_as_uint(Vs[(kt * 8 + tg + 4) * VSTR + nt * 8 + g]);
                mma_tf32(ofr[nt], pa0, pa1, pa2, pa3, b0, b1);
            }
        }
    }

    // Epilogue: normalize, convert to half for out-proj GEMM
    const float inv0 = 1.0f / l0;
    const float inv1 = 1.0f / l1;
    __half* yrow = Y + ((size_t)(b * Sn + row0)) * Dn + h * DHn;
#pragma unroll
    for (int nt = 0; nt < 16; nt++) {
        const int col = nt * 8 + 2 * tg;
        __half2 h0 = __floats2half2_rn(ofr[nt][0] * inv0, ofr[nt][1] * inv0);
        __half2 h1 = __floats2half2_rn(ofr[nt][2] * inv1, ofr[nt][3] * inv1);
        *(__half2*)&yrow[col] = h0;
        *(__half2*)&yrow[(size_t)8 * Dn + col] = h1;
    }
}

// ---------------------------------------------------------------------------
extern "C" void kernel_launch(void* const* d_in, const int* in_sizes, int n_in,
                              void* d_out, int out_size)
{
    (void)in_sizes; (void)n_in; (void)out_size;
    const float* x      = (const float*)d_in[0];
    const float* qkv_w  = (const float*)d_in[1];
    const float* qkv_b  = (const float*)d_in[2];
    const float* out_w  = (const float*)d_in[3];
    const float* out_b  = (const float*)d_in[4];
    float* out = (float*)d_out;

    float* qkv;
    __half *y, *xt, *wq, *wo;
    cudaGetSymbolAddress((void**)&qkv, g_qkv);
    cudaGetSymbolAddress((void**)&y, g_y);
    cudaGetSymbolAddress((void**)&xt, g_xt);
    cudaGetSymbolAddress((void**)&wq, g_wq);
    cudaGetSymbolAddress((void**)&wo, g_wo);

    cudaFuncSetAttribute(mma_gemm_h,
                         cudaFuncAttributeMaxDynamicSharedMemorySize, GEMM2_SMEM);
    cudaFuncSetAttribute(flash_attn_tc,
                         cudaFuncAttributeMaxDynamicSharedMemorySize, FA_SMEM);

    // 0) Pre-convert inputs to fp16
    {
        int n8x = (NROWS * Dn) / 8;
        conv_h_kernel<<<(n8x + 255) / 256, 256>>>(x, xt, n8x);
        int n8q = (TDn * Dn) / 8;
        conv_h_kernel<<<(n8q + 255) / 256, 256>>>(qkv_w, wq, n8q);
        int n8o = (Dn * Dn) / 8;
        conv_h_kernel<<<(n8o + 255) / 256, 256>>>(out_w, wo, n8o);
    }

    // 1) QKV projection + fused RoPE (fp16 mma)
    {
        dim3 grid(TDn / 128, NROWS / 128);
        mma_gemm_h<<<grid, 128, GEMM2_SMEM>>>(xt, wq, qkv_b, qkv,
                                              NROWS, TDn, Dn, 1);
    }

    // 2) Flash attention (tensor-core tf32, R7 structure), emits half y
    {
        dim3 grid(Sn / 128, Bn * Hn);
        flash_attn_tc<<<grid, 256, FA_SMEM>>>(qkv, y);
    }

    // 3) Output projection (fp16 mma)
    {
        dim3 grid(Dn / 128, NROWS / 128);
        mma_gemm_h<<<grid, 128, GEMM2_SMEM>>>(y, wo, out_b, out,
                                              NROWS, Dn, Dn, 0);
    }
}

// round 11
// speedup vs baseline: 1.8741x; 1.1582x over previous
#include <cuda_runtime.h>
#include <cuda_fp16.h>
#include <cstdint>
#include <math.h>

// Problem constants
#define Bn 4
#define Sn 2048
#define Dn 2048
#define Hn 16
#define DHn 128
#define TDn 6144            // 3*D
#define NROWS (Bn*Sn)       // 8192

#define ATTN_SCALE 0.08838834764831845f

// Scratch (device globals; no cudaMalloc allowed)
__device__ __half g_qkv[(size_t)NROWS * TDn];   // 100 MB half (RoPE'd, q scaled)
__device__ __half g_y[(size_t)NROWS * Dn];      // 33 MB  half (attn out)
__device__ __half g_xt[(size_t)NROWS * Dn];     // 33 MB  x  half
__device__ __half g_wq[(size_t)TDn * Dn];       // 25 MB  qkv_w half
__device__ __half g_wo[(size_t)Dn * Dn];        // 8 MB   out_w half

__device__ __forceinline__ void mma_f16(float* d,
                                        uint32_t a0, uint32_t a1,
                                        uint32_t a2, uint32_t a3,
                                        uint32_t b0, uint32_t b1) {
    asm volatile(
        "mma.sync.aligned.m16n8k16.row.col.f32.f16.f16.f32 "
        "{%0,%1,%2,%3}, {%4,%5,%6,%7}, {%8,%9}, {%0,%1,%2,%3};"
        : "+f"(d[0]), "+f"(d[1]), "+f"(d[2]), "+f"(d[3])
        : "r"(a0), "r"(a1), "r"(a2), "r"(a3), "r"(b0), "r"(b1));
}

__device__ __forceinline__ void ldsm4t(uint32_t& r0, uint32_t& r1,
                                       uint32_t& r2, uint32_t& r3,
                                       const __half* p) {
    uint32_t a = (uint32_t)__cvta_generic_to_shared(p);
    asm volatile(
        "ldmatrix.sync.aligned.m8n8.x4.trans.shared.b16 {%0,%1,%2,%3}, [%4];"
        : "=r"(r0), "=r"(r1), "=r"(r2), "=r"(r3) : "r"(a));
}

__device__ __forceinline__ void cp16(void* smem_ptr, const void* gptr) {
    uint32_t sa = (uint32_t)__cvta_generic_to_shared(smem_ptr);
    asm volatile("cp.async.cg.shared.global [%0], [%1], 16;"
                 :: "r"(sa), "l"(gptr));
}
#define CP_COMMIT() asm volatile("cp.async.commit_group;" ::: "memory")
#define CP_WAIT(n)  asm volatile("cp.async.wait_group %0;" :: "n"(n) : "memory")

// ---------------------------------------------------------------------------
// Pre-convert fp32 -> fp16 (8 elems/thread)
// ---------------------------------------------------------------------------
__global__ __launch_bounds__(256) void conv_h_kernel(
    const float* __restrict__ in, __half* __restrict__ out, int n8)
{
    int i = blockIdx.x * blockDim.x + threadIdx.x;
    if (i >= n8) return;
    float4 v0 = ((const float4*)in)[2 * i];
    float4 v1 = ((const float4*)in)[2 * i + 1];
    __half2 h0 = __floats2half2_rn(v0.x, v0.y);
    __half2 h1 = __floats2half2_rn(v0.z, v0.w);
    __half2 h2 = __floats2half2_rn(v1.x, v1.y);
    __half2 h3 = __floats2half2_rn(v1.z, v1.w);
    uint4 u;
    u.x = *(uint32_t*)&h0; u.y = *(uint32_t*)&h1;
    u.z = *(uint32_t*)&h2; u.w = *(uint32_t*)&h3;
    ((uint4*)out)[i] = u;
}

// ---------------------------------------------------------------------------
// fp16 mma GEMM: C = A @ W^T + bias.
// qkv_mode: fused RoPE on q,k cols, q pre-scaled by 1/sqrt(dh), HALF output.
// else: fp32 output.
// CTA 128x128, 128 threads = 4 warps (2m x 2n), warp tile 64x64.
// KC=32 halves, 4 stages, stride-40-half smem. 2 CTAs/SM.
// ---------------------------------------------------------------------------
#define KC2 32
#define STG 4
#define STRH 40
#define ATILE_H (128 * STRH)
#define STAGE_H (2 * ATILE_H)
#define GEMM2_SMEM (STG * STAGE_H * 2)        // 81920 bytes

__global__ void __launch_bounds__(128, 2) mma_gemm_h(
    const __half* __restrict__ A, const __half* __restrict__ W,
    const float* __restrict__ bias, float* __restrict__ Cf,
    __half* __restrict__ Ch,
    int M, int N, int K, int qkv_mode)
{
    extern __shared__ __half smh[];
    const int tid = threadIdx.x;
    const int wid = tid >> 5;
    const int lid = tid & 31;
    const int g   = lid >> 2;
    const int tg  = lid & 3;
    const int wm  = wid >> 1;
    const int wn  = wid & 1;
    const int m0 = blockIdx.y << 7;
    const int n0 = blockIdx.x << 7;

    const __half* Abase = A + (size_t)m0 * K;
    const __half* Wbase = W + (size_t)n0 * K;

    float acc[4][8][4];
#pragma unroll
    for (int mi = 0; mi < 4; mi++)
#pragma unroll
        for (int ni = 0; ni < 8; ni++)
#pragma unroll
            for (int r = 0; r < 4; r++) acc[mi][ni][r] = 0.f;

    const int nc = K / KC2;

    auto issue_load = [&](int stage, int chunk) {
        const int k0 = chunk * KC2;
        __half* As = smh + stage * STAGE_H;
        __half* Bs = As + ATILE_H;
#pragma unroll
        for (int i = 0; i < 4; i++) {
            const int idx = i * 128 + tid;
            const int row = idx >> 2;
            const int s8  = (idx & 3) << 3;
            cp16(&As[row * STRH + s8], Abase + (size_t)row * K + k0 + s8);
            cp16(&Bs[row * STRH + s8], Wbase + (size_t)row * K + k0 + s8);
        }
    };

    auto compute = [&](int stage) {
        const __half* As = smh + stage * STAGE_H;
        const __half* Bs = As + ATILE_H;
#pragma unroll
        for (int ks = 0; ks < 2; ks++) {
            const int kc = ks * 16;
            uint32_t bf[8][2];
#pragma unroll
            for (int ni = 0; ni < 8; ni++) {
                const __half* bp = &Bs[(wn * 64 + ni * 8 + g) * STRH + kc + 2 * tg];
                bf[ni][0] = *(const uint32_t*)bp;
                bf[ni][1] = *(const uint32_t*)(bp + 8);
            }
#pragma unroll
            for (int mi = 0; mi < 4; mi++) {
                const __half* ap = &As[(wm * 64 + mi * 16 + g) * STRH + kc + 2 * tg];
                uint32_t a0 = *(const uint32_t*)ap;
                uint32_t a1 = *(const uint32_t*)(ap + 8 * STRH);
                uint32_t a2 = *(const uint32_t*)(ap + 8);
                uint32_t a3 = *(const uint32_t*)(ap + 8 * STRH + 8);
#pragma unroll
                for (int ni = 0; ni < 8; ni++)
                    mma_f16(acc[mi][ni], a0, a1, a2, a3,
                            bf[ni][0], bf[ni][1]);
            }
        }
    };

#pragma unroll
    for (int s = 0; s < STG - 1; s++) {
        issue_load(s, s);
        CP_COMMIT();
    }

    for (int c = 0; c < nc; c++) {
        CP_WAIT(STG - 2);
        __syncthreads();
        const int nxt = c + STG - 1;
        if (nxt < nc) issue_load(nxt & (STG - 1), nxt);
        CP_COMMIT();
        compute(c & (STG - 1));
    }

    // epilogue
    const bool do_rope = qkv_mode && (n0 < 2 * Dn);
    const float qs = (qkv_mode && n0 < Dn) ? ATTN_SCALE : 1.0f;
#pragma unroll
    for (int ni = 0; ni < 8; ni++) {
        const int col = n0 + wn * 64 + ni * 8 + 2 * tg;
        const float2 bj = *(const float2*)&bias[col];
        float freq = 0.f;
        if (do_rope) {
            const int d2 = (col & 127) >> 1;
            freq = powf(10000.0f, -(float)d2 / 64.0f);
        }
#pragma unroll
        for (int mi = 0; mi < 4; mi++) {
            const int row = m0 + wm * 64 + mi * 16 + g;
            float2 o0, o1;
            o0.x = acc[mi][ni][0] + bj.x;
            o0.y = acc[mi][ni][1] + bj.y;
            o1.x = acc[mi][ni][2] + bj.x;
            o1.y = acc[mi][ni][3] + bj.y;
            if (do_rope) {
                float sn, cs;
                float omega = (float)(row & (Sn - 1)) * freq;
                sincosf(omega, &sn, &cs);
                float r0x = o0.x * cs - o0.y * sn;
                float r0y = o0.x * sn + o0.y * cs;
                o0.x = r0x; o0.y = r0y;
                omega = (float)((row + 8) & (Sn - 1)) * freq;
                sincosf(omega, &sn, &cs);
                float r1x = o1.x * cs - o1.y * sn;
                float r1y = o1.x * sn + o1.y * cs;
                o1.x = r1x; o1.y = r1y;
            }
            if (qkv_mode) {
                __half2 h0 = __floats2half2_rn(o0.x * qs, o0.y * qs);
                __half2 h1 = __floats2half2_rn(o1.x * qs, o1.y * qs);
                *(__half2*)&Ch[(size_t)row * N + col] = h0;
                *(__half2*)&Ch[(size_t)(row + 8) * N + col] = h1;
            } else {
                *(float2*)&Cf[(size_t)row * N + col] = o0;
                *(float2*)&Cf[(size_t)(row + 8) * N + col] = o1;
            }
        }
    }
}

// ---------------------------------------------------------------------------
// Tensor-core flash attention (causal), fp16 mma m16n8k16.
// Input qkv: half, RoPE'd, q pre-scaled. Output y: half.
// CTA: 128 q-rows, 8 warps x 16 rows. K-tile 64 keys.
// K/V row-major half in smem (stride 136); V B-frags via ldmatrix.trans.
// ---------------------------------------------------------------------------
#define KSTR_H 136
#define PSTR_H 136
#define FA_SMEM ((64 * KSTR_H * 2 + 128 * PSTR_H) * 2)   // 69632 bytes

__global__ __launch_bounds__(256) void flash_attn_tc(
    const __half* __restrict__ qkv, __half* __restrict__ Y)
{
    extern __shared__ __half smh[];
    __half* Ks = smh;
    __half* Vs = Ks + 64 * KSTR_H;
    __half* Pw = Vs + 64 * KSTR_H;

    const int tid = threadIdx.x;
    const int wid = tid >> 5;
    const int lid = tid & 31;
    const int g   = lid >> 2;
    const int tg  = lid & 3;
    const int qb  = blockIdx.x;
    const int q0  = qb * 128;
    const int bh  = blockIdx.y;
    const int b   = bh >> 4;
    const int h   = bh & 15;

    const int row0 = q0 + wid * 16 + g;

    // Q fragments (q already scaled + RoPE'd + half in gmem)
    const __half* qptr = qkv + ((size_t)(b * Sn + row0)) * TDn + h * DHn;
    uint32_t qf[8][4];
#pragma unroll
    for (int kt = 0; kt < 8; kt++) {
        qf[kt][0] = *(const uint32_t*)(qptr + kt * 16 + 2 * tg);
        qf[kt][1] = *(const uint32_t*)(qptr + (size_t)8 * TDn + kt * 16 + 2 * tg);
        qf[kt][2] = *(const uint32_t*)(qptr + kt * 16 + 8 + 2 * tg);
        qf[kt][3] = *(const uint32_t*)(qptr + (size_t)8 * TDn + kt * 16 + 8 + 2 * tg);
    }

    float ofr[16][4];
#pragma unroll
    for (int nt = 0; nt < 16; nt++)
#pragma unroll
        for (int r = 0; r < 4; r++) ofr[nt][r] = 0.f;

    float m0 = -1e30f, m1 = -1e30f, l0 = 0.f, l1 = 0.f;

    const __half* kbase = qkv + ((size_t)(b * Sn)) * TDn + Dn + h * DHn;
    const __half* vbase = kbase + Dn;
    __half* prow = Pw + (wid * 16) * PSTR_H;

    const int ldi = lid >> 3;   // ldmatrix matrix index 0..3
    const int ldj = lid & 7;    // row within matrix

    const int nkb = 2 * qb + 2;
    for (int kb = 0; kb < nkb; kb++) {
        __syncthreads();
        const int k0 = kb * 64;

        // Load K,V tiles (half, no conversion). 64 rows x 128 halves each.
#pragma unroll
        for (int i = 0; i < 4; i++) {
            int idx = tid + i * 256;
            int r  = idx >> 4;            // 0..63
            int s8 = (idx & 15) << 3;     // 0..120
            const size_t go = (size_t)(k0 + r) * TDn + s8;
            *(uint4*)&Ks[r * KSTR_H + s8] = *(const uint4*)(kbase + go);
            *(uint4*)&Vs[r * KSTR_H + s8] = *(const uint4*)(vbase + go);
        }
        __syncthreads();

        // S = Q K^T (fp16 mma, fp32 accum). 8 k-steps of 16.
        float sc[8][4];
#pragma unroll
        for (int nt = 0; nt < 8; nt++)
#pragma unroll
            for (int r = 0; r < 4; r++) sc[nt][r] = 0.f;

#pragma unroll
        for (int kt = 0; kt < 8; kt++) {
#pragma unroll
            for (int nt = 0; nt < 8; nt++) {
                const __half* bp = &Ks[(nt * 8 + g) * KSTR_H + kt * 16 + 2 * tg];
                uint32_t b0 = *(const uint32_t*)bp;
                uint32_t b1 = *(const uint32_t*)(bp + 8);
                mma_f16(sc[nt], qf[kt][0], qf[kt][1], qf[kt][2], qf[kt][3],
                        b0, b1);
            }
        }

        // Causal mask
        if (kb >= 2 * qb) {
#pragma unroll
            for (int nt = 0; nt < 8; nt++) {
                int col = k0 + nt * 8 + 2 * tg;
                if (col > row0)     sc[nt][0] = -1e30f;
                if (col + 1 > row0) sc[nt][1] = -1e30f;
                if (col > row0 + 8)     sc[nt][2] = -1e30f;
                if (col + 1 > row0 + 8) sc[nt][3] = -1e30f;
            }
        }

        // Online softmax
        float mx0 = -1e30f, mx1 = -1e30f;
#pragma unroll
        for (int nt = 0; nt < 8; nt++) {
            mx0 = fmaxf(mx0, fmaxf(sc[nt][0], sc[nt][1]));
            mx1 = fmaxf(mx1, fmaxf(sc[nt][2], sc[nt][3]));
        }
        mx0 = fmaxf(mx0, __shfl_xor_sync(0xffffffffu, mx0, 1));
        mx0 = fmaxf(mx0, __shfl_xor_sync(0xffffffffu, mx0, 2));
        mx1 = fmaxf(mx1, __shfl_xor_sync(0xffffffffu, mx1, 1));
        mx1 = fmaxf(mx1, __shfl_xor_sync(0xffffffffu, mx1, 2));

        const float mn0 = fmaxf(m0, mx0);
        const float mn1 = fmaxf(m1, mx1);
        const float a0 = __expf(m0 - mn0);
        const float a1 = __expf(m1 - mn1);
        m0 = mn0; m1 = mn1;

        float s0 = 0.f, s1 = 0.f;
#pragma unroll
        for (int nt = 0; nt < 8; nt++) {
            sc[nt][0] = __expf(sc[nt][0] - mn0);
            sc[nt][1] = __expf(sc[nt][1] - mn0);
            sc[nt][2] = __expf(sc[nt][2] - mn1);
            sc[nt][3] = __expf(sc[nt][3] - mn1);
            s0 += sc[nt][0] + sc[nt][1];
            s1 += sc[nt][2] + sc[nt][3];
        }
        s0 += __shfl_xor_sync(0xffffffffu, s0, 1);
        s0 += __shfl_xor_sync(0xffffffffu, s0, 2);
        s1 += __shfl_xor_sync(0xffffffffu, s1, 1);
        s1 += __shfl_xor_sync(0xffffffffu, s1, 2);
        l0 = l0 * a0 + s0;
        l1 = l1 * a1 + s1;

#pragma unroll
        for (int nt = 0; nt < 16; nt++) {
            ofr[nt][0] *= a0; ofr[nt][1] *= a0;
            ofr[nt][2] *= a1; ofr[nt][3] *= a1;
        }

        // Write P (half) to warp-private smem
        __syncwarp();
#pragma unroll
        for (int nt = 0; nt < 8; nt++) {
            const int col = nt * 8 + 2 * tg;
            *(__half2*)&prow[g * PSTR_H + col] =
                __floats2half2_rn(sc[nt][0], sc[nt][1]);
            *(__half2*)&prow[(g + 8) * PSTR_H + col] =
                __floats2half2_rn(sc[nt][2], sc[nt][3]);
        }
        __syncwarp();

        // O += P @ V : A-frags from P (half), B-frags via ldmatrix.trans on Vs
#pragma unroll
        for (int kt = 0; kt < 4; kt++) {
            uint32_t pa0 = *(const uint32_t*)&prow[g * PSTR_H + kt * 16 + 2 * tg];
            uint32_t pa1 = *(const uint32_t*)&prow[(g + 8) * PSTR_H + kt * 16 + 2 * tg];
            uint32_t pa2 = *(const uint32_t*)&prow[g * PSTR_H + kt * 16 + 8 + 2 * tg];
            uint32_t pa3 = *(const uint32_t*)&prow[(g + 8) * PSTR_H + kt * 16 + 8 + 2 * tg];
            const int vrow = kt * 16 + (ldi & 1) * 8 + ldj;
#pragma unroll
            for (int ntp = 0; ntp < 8; ntp++) {
                uint32_t r0, r1, r2, r3;
                ldsm4t(r0, r1, r2, r3,
                       &Vs[vrow * KSTR_H + ntp * 16 + (ldi >> 1) * 8]);
                mma_f16(ofr[2 * ntp],     pa0, pa1, pa2, pa3, r0, r1);
                mma_f16(ofr[2 * ntp + 1], pa0, pa1, pa2, pa3, r2, r3);
            }
        }
    }

    // Epilogue: normalize, emit half y
    const float inv0 = 1.0f / l0;
    const float inv1 = 1.0f / l1;
    __half* yrow = Y + ((size_t)(b * Sn + row0)) * Dn + h * DHn;
#pragma unroll
    for (int nt = 0; nt < 16; nt++) {
        const int col = nt * 8 + 2 * tg;
        __half2 h0 = __floats2half2_rn(ofr[nt][0] * inv0, ofr[nt][1] * inv0);
        __half2 h1 = __floats2half2_rn(ofr[nt][2] * inv1, ofr[nt][3] * inv1);
        *(__half2*)&yrow[col] = h0;
        *(__half2*)&yrow[(size_t)8 * Dn + col] = h1;
    }
}

// ---------------------------------------------------------------------------
extern "C" void kernel_launch(void* const* d_in, const int* in_sizes, int n_in,
                              void* d_out, int out_size)
{
    (void)in_sizes; (void)n_in; (void)out_size;
    const float* x      = (const float*)d_in[0];
    const float* qkv_w  = (const float*)d_in[1];
    const float* qkv_b  = (const float*)d_in[2];
    const float* out_w  = (const float*)d_in[3];
    const float* out_b  = (const float*)d_in[4];
    float* out = (float*)d_out;

    __half *qkv, *y, *xt, *wq, *wo;
    cudaGetSymbolAddress((void**)&qkv, g_qkv);
    cudaGetSymbolAddress((void**)&y, g_y);
    cudaGetSymbolAddress((void**)&xt, g_xt);
    cudaGetSymbolAddress((void**)&wq, g_wq);
    cudaGetSymbolAddress((void**)&wo, g_wo);

    cudaFuncSetAttribute(mma_gemm_h,
                         cudaFuncAttributeMaxDynamicSharedMemorySize, GEMM2_SMEM);
    cudaFuncSetAttribute(flash_attn_tc,
                         cudaFuncAttributeMaxDynamicSharedMemorySize, FA_SMEM);

    // 0) Pre-convert inputs to fp16
    {
        int n8x = (NROWS * Dn) / 8;
        conv_h_kernel<<<(n8x + 255) / 256, 256>>>(x, xt, n8x);
        int n8q = (TDn * Dn) / 8;
        conv_h_kernel<<<(n8q + 255) / 256, 256>>>(qkv_w, wq, n8q);
        int n8o = (Dn * Dn) / 8;
        conv_h_kernel<<<(n8o + 255) / 256, 256>>>(out_w, wo, n8o);
    }

    // 1) QKV projection + fused RoPE + q-scale, half output
    {
        dim3 grid(TDn / 128, NROWS / 128);
        mma_gemm_h<<<grid, 128, GEMM2_SMEM>>>(xt, wq, qkv_b, nullptr, qkv,
                                              NROWS, TDn, Dn, 1);
    }

    // 2) Flash attention (fp16 mma), emits half y
    {
        dim3 grid(Sn / 128, Bn * Hn);
        flash_attn_tc<<<grid, 256, FA_SMEM>>>(qkv, y);
    }

    // 3) Output projection (fp16 mma, fp32 output)
    {
        dim3 grid(Dn / 128, NROWS / 128);
        mma_gemm_h<<<grid, 128, GEMM2_SMEM>>>(y, wo, out_b, out, nullptr,
                                              NROWS, Dn, Dn, 0);
    }
}

// round 12
// speedup vs baseline: 2.1135x; 1.1278x over previous
#include <cuda_runtime.h>
#include <cuda_fp16.h>
#include <cstdint>
#include <math.h>

// Problem constants
#define Bn 4
#define Sn 2048
#define Dn 2048
#define Hn 16
#define DHn 128
#define TDn 6144            // 3*D
#define NROWS (Bn*Sn)       // 8192

#define ATTN_SCALE 0.08838834764831845f

// Scratch (device globals; no cudaMalloc allowed)
__device__ __half g_qkv[(size_t)NROWS * TDn];   // 100 MB half (RoPE'd, q scaled)
__device__ __half g_y[(size_t)NROWS * Dn];      // 33 MB  half (attn out)
__device__ __half g_xt[(size_t)NROWS * Dn];     // 33 MB  x  half
__device__ __half g_wq[(size_t)TDn * Dn];       // 25 MB  qkv_w half
__device__ __half g_wo[(size_t)Dn * Dn];        // 8 MB   out_w half

__device__ __forceinline__ void mma_f16(float* d,
                                        uint32_t a0, uint32_t a1,
                                        uint32_t a2, uint32_t a3,
                                        uint32_t b0, uint32_t b1) {
    asm volatile(
        "mma.sync.aligned.m16n8k16.row.col.f32.f16.f16.f32 "
        "{%0,%1,%2,%3}, {%4,%5,%6,%7}, {%8,%9}, {%0,%1,%2,%3};"
        : "+f"(d[0]), "+f"(d[1]), "+f"(d[2]), "+f"(d[3])
        : "r"(a0), "r"(a1), "r"(a2), "r"(a3), "r"(b0), "r"(b1));
}

__device__ __forceinline__ void ldsm4(uint32_t& r0, uint32_t& r1,
                                      uint32_t& r2, uint32_t& r3,
                                      const __half* p) {
    uint32_t a = (uint32_t)__cvta_generic_to_shared(p);
    asm volatile(
        "ldmatrix.sync.aligned.m8n8.x4.shared.b16 {%0,%1,%2,%3}, [%4];"
        : "=r"(r0), "=r"(r1), "=r"(r2), "=r"(r3) : "r"(a));
}

__device__ __forceinline__ void ldsm4t(uint32_t& r0, uint32_t& r1,
                                       uint32_t& r2, uint32_t& r3,
                                       const __half* p) {
    uint32_t a = (uint32_t)__cvta_generic_to_shared(p);
    asm volatile(
        "ldmatrix.sync.aligned.m8n8.x4.trans.shared.b16 {%0,%1,%2,%3}, [%4];"
        : "=r"(r0), "=r"(r1), "=r"(r2), "=r"(r3) : "r"(a));
}

__device__ __forceinline__ void cp16(void* smem_ptr, const void* gptr) {
    uint32_t sa = (uint32_t)__cvta_generic_to_shared(smem_ptr);
    asm volatile("cp.async.cg.shared.global [%0], [%1], 16;"
                 :: "r"(sa), "l"(gptr));
}
#define CP_COMMIT() asm volatile("cp.async.commit_group;" ::: "memory")
#define CP_WAIT(n)  asm volatile("cp.async.wait_group %0;" :: "n"(n) : "memory")

// ---------------------------------------------------------------------------
// Pre-convert fp32 -> fp16 (8 elems/thread)
// ---------------------------------------------------------------------------
__global__ __launch_bounds__(256) void conv_h_kernel(
    const float* __restrict__ in, __half* __restrict__ out, int n8)
{
    int i = blockIdx.x * blockDim.x + threadIdx.x;
    if (i >= n8) return;
    float4 v0 = ((const float4*)in)[2 * i];
    float4 v1 = ((const float4*)in)[2 * i + 1];
    __half2 h0 = __floats2half2_rn(v0.x, v0.y);
    __half2 h1 = __floats2half2_rn(v0.z, v0.w);
    __half2 h2 = __floats2half2_rn(v1.x, v1.y);
    __half2 h3 = __floats2half2_rn(v1.z, v1.w);
    uint4 u;
    u.x = *(uint32_t*)&h0; u.y = *(uint32_t*)&h1;
    u.z = *(uint32_t*)&h2; u.w = *(uint32_t*)&h3;
    ((uint4*)out)[i] = u;
}

// ---------------------------------------------------------------------------
// fp16 mma GEMM with ldmatrix fragments.
// qkv_mode: fused RoPE on q,k cols, q pre-scaled, HALF output; else fp32.
// CTA 128x128, 128 threads = 4 warps (2m x 2n), warp tile 64x64.
// KC=64 halves, 3 stages, stride-72-half smem (conflict-free). 2 CTAs/SM.
// ---------------------------------------------------------------------------
#define KC2 64
#define STG 3
#define STRH 72
#define ATILE_H (128 * STRH)                  // 9216 halves (18KB)
#define STAGE_H (2 * ATILE_H)
#define GEMM2_SMEM (STG * STAGE_H * 2)        // 110592 bytes

__global__ void __launch_bounds__(128, 2) mma_gemm_h(
    const __half* __restrict__ A, const __half* __restrict__ W,
    const float* __restrict__ bias, float* __restrict__ Cf,
    __half* __restrict__ Ch,
    int M, int N, int K, int qkv_mode)
{
    extern __shared__ __half smh[];
    const int tid = threadIdx.x;
    const int wid = tid >> 5;
    const int lid = tid & 31;
    const int g   = lid >> 2;
    const int tg  = lid & 3;
    const int wm  = wid >> 1;
    const int wn  = wid & 1;
    const int m0 = blockIdx.y << 7;
    const int n0 = blockIdx.x << 7;

    // ldmatrix lane addressing
    const int i4 = lid >> 3;            // matrix index 0..3
    const int j8 = lid & 7;             // row within matrix
    const int a_r = (i4 & 1) * 8 + j8;  // A: m offset within 16-row tile
    const int a_c = (i4 >> 1) * 8;      // A: k offset within 16
    const int b_r = (i4 >> 1) * 8 + j8; // B: n offset within 16-row pair
    const int b_c = (i4 & 1) * 8;       // B: k offset within 16

    const __half* Abase = A + (size_t)m0 * K;
    const __half* Wbase = W + (size_t)n0 * K;

    float acc[4][8][4];
#pragma unroll
    for (int mi = 0; mi < 4; mi++)
#pragma unroll
        for (int ni = 0; ni < 8; ni++)
#pragma unroll
            for (int r = 0; r < 4; r++) acc[mi][ni][r] = 0.f;

    const int nc = K / KC2;

    auto issue_load = [&](int stage, int chunk) {
        const int k0 = chunk * KC2;
        __half* As = smh + stage * STAGE_H;
        __half* Bs = As + ATILE_H;
#pragma unroll
        for (int i = 0; i < 8; i++) {
            const int idx = i * 128 + tid;
            const int row = idx >> 3;            // 0..127
            const int s8  = (idx & 7) << 3;      // 0..56 halves
            cp16(&As[row * STRH + s8], Abase + (size_t)row * K + k0 + s8);
            cp16(&Bs[row * STRH + s8], Wbase + (size_t)row * K + k0 + s8);
        }
    };

    auto compute = [&](int stage) {
        const __half* As = smh + stage * STAGE_H;
        const __half* Bs = As + ATILE_H;
#pragma unroll
        for (int ks = 0; ks < 4; ks++) {
            const int kc = ks * 16;
            uint32_t bf[8][2];
#pragma unroll
            for (int nip = 0; nip < 4; nip++) {
                uint32_t r0, r1, r2, r3;
                ldsm4(r0, r1, r2, r3,
                      &Bs[(wn * 64 + nip * 16 + b_r) * STRH + kc + b_c]);
                bf[2 * nip][0]     = r0; bf[2 * nip][1]     = r1;
                bf[2 * nip + 1][0] = r2; bf[2 * nip + 1][1] = r3;
            }
#pragma unroll
            for (int mi = 0; mi < 4; mi++) {
                uint32_t a0, a1, a2, a3;
                ldsm4(a0, a1, a2, a3,
                      &As[(wm * 64 + mi * 16 + a_r) * STRH + kc + a_c]);
#pragma unroll
                for (int ni = 0; ni < 8; ni++)
                    mma_f16(acc[mi][ni], a0, a1, a2, a3,
                            bf[ni][0], bf[ni][1]);
            }
        }
    };

#pragma unroll
    for (int s = 0; s < STG - 1; s++) {
        issue_load(s, s);
        CP_COMMIT();
    }

    int st = 0;                     // stage of chunk c
    for (int c = 0; c < nc; c++) {
        CP_WAIT(STG - 2);
        __syncthreads();
        const int nxt = c + STG - 1;
        if (nxt < nc) {
            int nst = st + STG - 1; if (nst >= STG) nst -= STG;
            issue_load(nst, nxt);
        }
        CP_COMMIT();
        compute(st);
        if (++st == STG) st = 0;
    }

    // epilogue
    const bool do_rope = qkv_mode && (n0 < 2 * Dn);
    const float qs = (qkv_mode && n0 < Dn) ? ATTN_SCALE : 1.0f;
#pragma unroll
    for (int ni = 0; ni < 8; ni++) {
        const int col = n0 + wn * 64 + ni * 8 + 2 * tg;
        const float2 bj = *(const float2*)&bias[col];
        float freq = 0.f;
        if (do_rope) {
            const int d2 = (col & 127) >> 1;
            freq = powf(10000.0f, -(float)d2 / 64.0f);
        }
#pragma unroll
        for (int mi = 0; mi < 4; mi++) {
            const int row = m0 + wm * 64 + mi * 16 + g;
            float2 o0, o1;
            o0.x = acc[mi][ni][0] + bj.x;
            o0.y = acc[mi][ni][1] + bj.y;
            o1.x = acc[mi][ni][2] + bj.x;
            o1.y = acc[mi][ni][3] + bj.y;
            if (do_rope) {
                float sn, cs;
                float omega = (float)(row & (Sn - 1)) * freq;
                sincosf(omega, &sn, &cs);
                float r0x = o0.x * cs - o0.y * sn;
                float r0y = o0.x * sn + o0.y * cs;
                o0.x = r0x; o0.y = r0y;
                omega = (float)((row + 8) & (Sn - 1)) * freq;
                sincosf(omega, &sn, &cs);
                float r1x = o1.x * cs - o1.y * sn;
                float r1y = o1.x * sn + o1.y * cs;
                o1.x = r1x; o1.y = r1y;
            }
            if (qkv_mode) {
                __half2 h0 = __floats2half2_rn(o0.x * qs, o0.y * qs);
                __half2 h1 = __floats2half2_rn(o1.x * qs, o1.y * qs);
                *(__half2*)&Ch[(size_t)row * N + col] = h0;
                *(__half2*)&Ch[(size_t)(row + 8) * N + col] = h1;
            } else {
                *(float2*)&Cf[(size_t)row * N + col] = o0;
                *(float2*)&Cf[(size_t)(row + 8) * N + col] = o1;
            }
        }
    }
}

// ---------------------------------------------------------------------------
// Tensor-core flash attention (causal), fp16 mma m16n8k16. (unchanged R11)
// ---------------------------------------------------------------------------
#define KSTR_H 136
#define PSTR_H 136
#define FA_SMEM ((64 * KSTR_H * 2 + 128 * PSTR_H) * 2)   // 69632 bytes

__global__ __launch_bounds__(256) void flash_attn_tc(
    const __half* __restrict__ qkv, __half* __restrict__ Y)
{
    extern __shared__ __half smh[];
    __half* Ks = smh;
    __half* Vs = Ks + 64 * KSTR_H;
    __half* Pw = Vs + 64 * KSTR_H;

    const int tid = threadIdx.x;
    const int wid = tid >> 5;
    const int lid = tid & 31;
    const int g   = lid >> 2;
    const int tg  = lid & 3;
    const int qb  = blockIdx.x;
    const int q0  = qb * 128;
    const int bh  = blockIdx.y;
    const int b   = bh >> 4;
    const int h   = bh & 15;

    const int row0 = q0 + wid * 16 + g;

    const __half* qptr = qkv + ((size_t)(b * Sn + row0)) * TDn + h * DHn;
    uint32_t qf[8][4];
#pragma unroll
    for (int kt = 0; kt < 8; kt++) {
        qf[kt][0] = *(const uint32_t*)(qptr + kt * 16 + 2 * tg);
        qf[kt][1] = *(const uint32_t*)(qptr + (size_t)8 * TDn + kt * 16 + 2 * tg);
        qf[kt][2] = *(const uint32_t*)(qptr + kt * 16 + 8 + 2 * tg);
        qf[kt][3] = *(const uint32_t*)(qptr + (size_t)8 * TDn + kt * 16 + 8 + 2 * tg);
    }

    float ofr[16][4];
#pragma unroll
    for (int nt = 0; nt < 16; nt++)
#pragma unroll
        for (int r = 0; r < 4; r++) ofr[nt][r] = 0.f;

    float m0 = -1e30f, m1 = -1e30f, l0 = 0.f, l1 = 0.f;

    const __half* kbase = qkv + ((size_t)(b * Sn)) * TDn + Dn + h * DHn;
    const __half* vbase = kbase + Dn;
    __half* prow = Pw + (wid * 16) * PSTR_H;

    const int ldi = lid >> 3;
    const int ldj = lid & 7;

    const int nkb = 2 * qb + 2;
    for (int kb = 0; kb < nkb; kb++) {
        __syncthreads();
        const int k0 = kb * 64;

#pragma unroll
        for (int i = 0; i < 4; i++) {
            int idx = tid + i * 256;
            int r  = idx >> 4;
            int s8 = (idx & 15) << 3;
            const size_t go = (size_t)(k0 + r) * TDn + s8;
            *(uint4*)&Ks[r * KSTR_H + s8] = *(const uint4*)(kbase + go);
            *(uint4*)&Vs[r * KSTR_H + s8] = *(const uint4*)(vbase + go);
        }
        __syncthreads();

        float sc[8][4];
#pragma unroll
        for (int nt = 0; nt < 8; nt++)
#pragma unroll
            for (int r = 0; r < 4; r++) sc[nt][r] = 0.f;

#pragma unroll
        for (int kt = 0; kt < 8; kt++) {
#pragma unroll
            for (int nt = 0; nt < 8; nt++) {
                const __half* bp = &Ks[(nt * 8 + g) * KSTR_H + kt * 16 + 2 * tg];
                uint32_t b0 = *(const uint32_t*)bp;
                uint32_t b1 = *(const uint32_t*)(bp + 8);
                mma_f16(sc[nt], qf[kt][0], qf[kt][1], qf[kt][2], qf[kt][3],
                        b0, b1);
            }
        }

        if (kb >= 2 * qb) {
#pragma unroll
            for (int nt = 0; nt < 8; nt++) {
                int col = k0 + nt * 8 + 2 * tg;
                if (col > row0)     sc[nt][0] = -1e30f;
                if (col + 1 > row0) sc[nt][1] = -1e30f;
                if (col > row0 + 8)     sc[nt][2] = -1e30f;
                if (col + 1 > row0 + 8) sc[nt][3] = -1e30f;
            }
        }

        float mx0 = -1e30f, mx1 = -1e30f;
#pragma unroll
        for (int nt = 0; nt < 8; nt++) {
            mx0 = fmaxf(mx0, fmaxf(sc[nt][0], sc[nt][1]));
            mx1 = fmaxf(mx1, fmaxf(sc[nt][2], sc[nt][3]));
        }
        mx0 = fmaxf(mx0, __shfl_xor_sync(0xffffffffu, mx0, 1));
        mx0 = fmaxf(mx0, __shfl_xor_sync(0xffffffffu, mx0, 2));
        mx1 = fmaxf(mx1, __shfl_xor_sync(0xffffffffu, mx1, 1));
        mx1 = fmaxf(mx1, __shfl_xor_sync(0xffffffffu, mx1, 2));

        const float mn0 = fmaxf(m0, mx0);
        const float mn1 = fmaxf(m1, mx1);
        const float a0 = __expf(m0 - mn0);
        const float a1 = __expf(m1 - mn1);
        m0 = mn0; m1 = mn1;

        float s0 = 0.f, s1 = 0.f;
#pragma unroll
        for (int nt = 0; nt < 8; nt++) {
            sc[nt][0] = __expf(sc[nt][0] - mn0);
            sc[nt][1] = __expf(sc[nt][1] - mn0);
            sc[nt][2] = __expf(sc[nt][2] - mn1);
            sc[nt][3] = __expf(sc[nt][3] - mn1);
            s0 += sc[nt][0] + sc[nt][1];
            s1 += sc[nt][2] + sc[nt][3];
        }
        s0 += __shfl_xor_sync(0xffffffffu, s0, 1);
        s0 += __shfl_xor_sync(0xffffffffu, s0, 2);
        s1 += __shfl_xor_sync(0xffffffffu, s1, 1);
        s1 += __shfl_xor_sync(0xffffffffu, s1, 2);
        l0 = l0 * a0 + s0;
        l1 = l1 * a1 + s1;

#pragma unroll
        for (int nt = 0; nt < 16; nt++) {
            ofr[nt][0] *= a0; ofr[nt][1] *= a0;
            ofr[nt][2] *= a1; ofr[nt][3] *= a1;
        }

        __syncwarp();
#pragma unroll
        for (int nt = 0; nt < 8; nt++) {
            const int col = nt * 8 + 2 * tg;
            *(__half2*)&prow[g * PSTR_H + col] =
                __floats2half2_rn(sc[nt][0], sc[nt][1]);
            *(__half2*)&prow[(g + 8) * PSTR_H + col] =
                __floats2half2_rn(sc[nt][2], sc[nt][3]);
        }
        __syncwarp();

#pragma unroll
        for (int kt = 0; kt < 4; kt++) {
            uint32_t pa0 = *(const uint32_t*)&prow[g * PSTR_H + kt * 16 + 2 * tg];
            uint32_t pa1 = *(const uint32_t*)&prow[(g + 8) * PSTR_H + kt * 16 + 2 * tg];
            uint32_t pa2 = *(const uint32_t*)&prow[g * PSTR_H + kt * 16 + 8 + 2 * tg];
            uint32_t pa3 = *(const uint32_t*)&prow[(g + 8) * PSTR_H + kt * 16 + 8 + 2 * tg];
            const int vrow = kt * 16 + (ldi & 1) * 8 + ldj;
#pragma unroll
            for (int ntp = 0; ntp < 8; ntp++) {
                uint32_t r0, r1, r2, r3;
                ldsm4t(r0, r1, r2, r3,
                       &Vs[vrow * KSTR_H + ntp * 16 + (ldi >> 1) * 8]);
                mma_f16(ofr[2 * ntp],     pa0, pa1, pa2, pa3, r0, r1);
                mma_f16(ofr[2 * ntp + 1], pa0, pa1, pa2, pa3, r2, r3);
            }
        }
    }

    const float inv0 = 1.0f / l0;
    const float inv1 = 1.0f / l1;
    __half* yrow = Y + ((size_t)(b * Sn + row0)) * Dn + h * DHn;
#pragma unroll
    for (int nt = 0; nt < 16; nt++) {
        const int col = nt * 8 + 2 * tg;
        __half2 h0 = __floats2half2_rn(ofr[nt][0] * inv0, ofr[nt][1] * inv0);
        __half2 h1 = __floats2half2_rn(ofr[nt][2] * inv1, ofr[nt][3] * inv1);
        *(__half2*)&yrow[col] = h0;
        *(__half2*)&yrow[(size_t)8 * Dn + col] = h1;
    }
}

// ---------------------------------------------------------------------------
extern "C" void kernel_launch(void* const* d_in, const int* in_sizes, int n_in,
                              void* d_out, int out_size)
{
    (void)in_sizes; (void)n_in; (void)out_size;
    const float* x      = (const float*)d_in[0];
    const float* qkv_w  = (const float*)d_in[1];
    const float* qkv_b  = (const float*)d_in[2];
    const float* out_w  = (const float*)d_in[3];
    const float* out_b  = (const float*)d_in[4];
    float* out = (float*)d_out;

    __half *qkv, *y, *xt, *wq, *wo;
    cudaGetSymbolAddress((void**)&qkv, g_qkv);
    cudaGetSymbolAddress((void**)&y, g_y);
    cudaGetSymbolAddress((void**)&xt, g_xt);
    cudaGetSymbolAddress((void**)&wq, g_wq);
    cudaGetSymbolAddress((void**)&wo, g_wo);

    cudaFuncSetAttribute(mma_gemm_h,
                         cudaFuncAttributeMaxDynamicSharedMemorySize, GEMM2_SMEM);
    cudaFuncSetAttribute(flash_attn_tc,
                         cudaFuncAttributeMaxDynamicSharedMemorySize, FA_SMEM);

    // 0) Pre-convert inputs to fp16
    {
        int n8x = (NROWS * Dn) / 8;
        conv_h_kernel<<<(n8x + 255) / 256, 256>>>(x, xt, n8x);
        int n8q = (TDn * Dn) / 8;
        conv_h_kernel<<<(n8q + 255) / 256, 256>>>(qkv_w, wq, n8q);
        int n8o = (Dn * Dn) / 8;
        conv_h_kernel<<<(n8o + 255) / 256, 256>>>(out_w, wo, n8o);
    }

    // 1) QKV projection + fused RoPE + q-scale, half output
    {
        dim3 grid(TDn / 128, NROWS / 128);
        mma_gemm_h<<<grid, 128, GEMM2_SMEM>>>(xt, wq, qkv_b, nullptr, qkv,
                                              NROWS, TDn, Dn, 1);
    }

    // 2) Flash attention (fp16 mma), emits half y
    {
        dim3 grid(Sn / 128, Bn * Hn);
        flash_attn_tc<<<grid, 256, FA_SMEM>>>(qkv, y);
    }

    // 3) Output projection (fp16 mma, fp32 output)
    {
        dim3 grid(Dn / 128, NROWS / 128);
        mma_gemm_h<<<grid, 128, GEMM2_SMEM>>>(y, wo, out_b, out, nullptr,
                                              NROWS, Dn, Dn, 0);
    }
}

// round 13
// speedup vs baseline: 2.2298x; 1.0550x over previous
#include <cuda_runtime.h>
#include <cuda_fp16.h>
#include <cstdint>
#include <math.h>

// Problem constants
#define Bn 4
#define Sn 2048
#define Dn 2048
#define Hn 16
#define DHn 128
#define TDn 6144            // 3*D
#define NROWS (Bn*Sn)       // 8192

#define ATTN_SCALE 0.08838834764831845f

// Scratch (device globals; no cudaMalloc allowed)
__device__ __half g_qkv[(size_t)NROWS * TDn];   // 100 MB half (RoPE'd, q scaled)
__device__ __half g_y[(size_t)NROWS * Dn];      // 33 MB  half (attn out)
__device__ __half g_xt[(size_t)NROWS * Dn];     // 33 MB  x  half
__device__ __half g_wq[(size_t)TDn * Dn];       // 25 MB  qkv_w half
__device__ __half g_wo[(size_t)Dn * Dn];        // 8 MB   out_w half

__device__ __forceinline__ void mma_f16(float* d,
                                        uint32_t a0, uint32_t a1,
                                        uint32_t a2, uint32_t a3,
                                        uint32_t b0, uint32_t b1) {
    asm volatile(
        "mma.sync.aligned.m16n8k16.row.col.f32.f16.f16.f32 "
        "{%0,%1,%2,%3}, {%4,%5,%6,%7}, {%8,%9}, {%0,%1,%2,%3};"
        : "+f"(d[0]), "+f"(d[1]), "+f"(d[2]), "+f"(d[3])
        : "r"(a0), "r"(a1), "r"(a2), "r"(a3), "r"(b0), "r"(b1));
}

__device__ __forceinline__ void ldsm4(uint32_t& r0, uint32_t& r1,
                                      uint32_t& r2, uint32_t& r3,
                                      const __half* p) {
    uint32_t a = (uint32_t)__cvta_generic_to_shared(p);
    asm volatile(
        "ldmatrix.sync.aligned.m8n8.x4.shared.b16 {%0,%1,%2,%3}, [%4];"
        : "=r"(r0), "=r"(r1), "=r"(r2), "=r"(r3) : "r"(a));
}

__device__ __forceinline__ void ldsm4t(uint32_t& r0, uint32_t& r1,
                                       uint32_t& r2, uint32_t& r3,
                                       const __half* p) {
    uint32_t a = (uint32_t)__cvta_generic_to_shared(p);
    asm volatile(
        "ldmatrix.sync.aligned.m8n8.x4.trans.shared.b16 {%0,%1,%2,%3}, [%4];"
        : "=r"(r0), "=r"(r1), "=r"(r2), "=r"(r3) : "r"(a));
}

__device__ __forceinline__ void cp16(void* smem_ptr, const void* gptr) {
    uint32_t sa = (uint32_t)__cvta_generic_to_shared(smem_ptr);
    asm volatile("cp.async.cg.shared.global [%0], [%1], 16;"
                 :: "r"(sa), "l"(gptr));
}
#define CP_COMMIT() asm volatile("cp.async.commit_group;" ::: "memory")
#define CP_WAIT(n)  asm volatile("cp.async.wait_group %0;" :: "n"(n) : "memory")

// ---------------------------------------------------------------------------
// Pre-convert fp32 -> fp16 (8 elems/thread)
// ---------------------------------------------------------------------------
__global__ __launch_bounds__(256) void conv_h_kernel(
    const float* __restrict__ in, __half* __restrict__ out, int n8)
{
    int i = blockIdx.x * blockDim.x + threadIdx.x;
    if (i >= n8) return;
    float4 v0 = ((const float4*)in)[2 * i];
    float4 v1 = ((const float4*)in)[2 * i + 1];
    __half2 h0 = __floats2half2_rn(v0.x, v0.y);
    __half2 h1 = __floats2half2_rn(v0.z, v0.w);
    __half2 h2 = __floats2half2_rn(v1.x, v1.y);
    __half2 h3 = __floats2half2_rn(v1.z, v1.w);
    uint4 u;
    u.x = *(uint32_t*)&h0; u.y = *(uint32_t*)&h1;
    u.z = *(uint32_t*)&h2; u.w = *(uint32_t*)&h3;
    ((uint4*)out)[i] = u;
}

// ---------------------------------------------------------------------------
// fp16 mma GEMM with ldmatrix fragments.
// qkv_mode: fused RoPE on q,k cols, q pre-scaled, HALF output; else fp32.
// CTA 128x128, 256 threads = 8 warps (2m x 4n), warp tile 64x32.
// KC=64 halves, 3 stages, stride-72-half smem (conflict-free). 2 CTAs/SM.
// ---------------------------------------------------------------------------
#define KC2 64
#define STG 3
#define STRH 72
#define ATILE_H (128 * STRH)                  // 9216 halves (18KB)
#define STAGE_H (2 * ATILE_H)
#define GEMM2_SMEM (STG * STAGE_H * 2)        // 110592 bytes

__global__ void __launch_bounds__(256, 2) mma_gemm_h(
    const __half* __restrict__ A, const __half* __restrict__ W,
    const float* __restrict__ bias, float* __restrict__ Cf,
    __half* __restrict__ Ch,
    int M, int N, int K, int qkv_mode)
{
    extern __shared__ __half smh[];
    const int tid = threadIdx.x;
    const int wid = tid >> 5;
    const int lid = tid & 31;
    const int g   = lid >> 2;
    const int tg  = lid & 3;
    const int wm  = wid >> 2;           // 0..1
    const int wn  = wid & 3;            // 0..3
    const int m0 = blockIdx.y << 7;
    const int n0 = blockIdx.x << 7;

    // ldmatrix lane addressing
    const int i4 = lid >> 3;            // matrix index 0..3
    const int j8 = lid & 7;             // row within matrix
    const int a_r = (i4 & 1) * 8 + j8;  // A: m offset within 16-row tile
    const int a_c = (i4 >> 1) * 8;      // A: k offset within 16
    const int b_r = (i4 >> 1) * 8 + j8; // B: n offset within 16-row pair
    const int b_c = (i4 & 1) * 8;       // B: k offset within 16

    const __half* Abase = A + (size_t)m0 * K;
    const __half* Wbase = W + (size_t)n0 * K;

    float acc[4][4][4];
#pragma unroll
    for (int mi = 0; mi < 4; mi++)
#pragma unroll
        for (int ni = 0; ni < 4; ni++)
#pragma unroll
            for (int r = 0; r < 4; r++) acc[mi][ni][r] = 0.f;

    const int nc = K / KC2;

    auto issue_load = [&](int stage, int chunk) {
        const int k0 = chunk * KC2;
        __half* As = smh + stage * STAGE_H;
        __half* Bs = As + ATILE_H;
#pragma unroll
        for (int i = 0; i < 4; i++) {
            const int idx = i * 256 + tid;
            const int row = idx >> 3;            // 0..127
            const int s8  = (idx & 7) << 3;      // 0..56 halves
            cp16(&As[row * STRH + s8], Abase + (size_t)row * K + k0 + s8);
            cp16(&Bs[row * STRH + s8], Wbase + (size_t)row * K + k0 + s8);
        }
    };

    auto compute = [&](int stage) {
        const __half* As = smh + stage * STAGE_H;
        const __half* Bs = As + ATILE_H;
#pragma unroll
        for (int ks = 0; ks < 4; ks++) {
            const int kc = ks * 16;
            uint32_t bf[4][2];
#pragma unroll
            for (int nip = 0; nip < 2; nip++) {
                uint32_t r0, r1, r2, r3;
                ldsm4(r0, r1, r2, r3,
                      &Bs[(wn * 32 + nip * 16 + b_r) * STRH + kc + b_c]);
                bf[2 * nip][0]     = r0; bf[2 * nip][1]     = r1;
                bf[2 * nip + 1][0] = r2; bf[2 * nip + 1][1] = r3;
            }
#pragma unroll
            for (int mi = 0; mi < 4; mi++) {
                uint32_t a0, a1, a2, a3;
                ldsm4(a0, a1, a2, a3,
                      &As[(wm * 64 + mi * 16 + a_r) * STRH + kc + a_c]);
#pragma unroll
                for (int ni = 0; ni < 4; ni++)
                    mma_f16(acc[mi][ni], a0, a1, a2, a3,
                            bf[ni][0], bf[ni][1]);
            }
        }
    };

#pragma unroll
    for (int s = 0; s < STG - 1; s++) {
        issue_load(s, s);
        CP_COMMIT();
    }

    int st = 0;
    for (int c = 0; c < nc; c++) {
        CP_WAIT(STG - 2);
        __syncthreads();
        const int nxt = c + STG - 1;
        if (nxt < nc) {
            int nst = st + STG - 1; if (nst >= STG) nst -= STG;
            issue_load(nst, nxt);
        }
        CP_COMMIT();
        compute(st);
        if (++st == STG) st = 0;
    }

    // epilogue
    const bool do_rope = qkv_mode && (n0 < 2 * Dn);
    const float qs = (qkv_mode && n0 < Dn) ? ATTN_SCALE : 1.0f;
#pragma unroll
    for (int ni = 0; ni < 4; ni++) {
        const int col = n0 + wn * 32 + ni * 8 + 2 * tg;
        const float2 bj = *(const float2*)&bias[col];
        float freq = 0.f;
        if (do_rope) {
            const int d2 = (col & 127) >> 1;
            freq = powf(10000.0f, -(float)d2 / 64.0f);
        }
#pragma unroll
        for (int mi = 0; mi < 4; mi++) {
            const int row = m0 + wm * 64 + mi * 16 + g;
            float2 o0, o1;
            o0.x = acc[mi][ni][0] + bj.x;
            o0.y = acc[mi][ni][1] + bj.y;
            o1.x = acc[mi][ni][2] + bj.x;
            o1.y = acc[mi][ni][3] + bj.y;
            if (do_rope) {
                float sn, cs;
                float omega = (float)(row & (Sn - 1)) * freq;
                sincosf(omega, &sn, &cs);
                float r0x = o0.x * cs - o0.y * sn;
                float r0y = o0.x * sn + o0.y * cs;
                o0.x = r0x; o0.y = r0y;
                omega = (float)((row + 8) & (Sn - 1)) * freq;
                sincosf(omega, &sn, &cs);
                float r1x = o1.x * cs - o1.y * sn;
                float r1y = o1.x * sn + o1.y * cs;
                o1.x = r1x; o1.y = r1y;
            }
            if (qkv_mode) {
                __half2 h0 = __floats2half2_rn(o0.x * qs, o0.y * qs);
                __half2 h1 = __floats2half2_rn(o1.x * qs, o1.y * qs);
                *(__half2*)&Ch[(size_t)row * N + col] = h0;
                *(__half2*)&Ch[(size_t)(row + 8) * N + col] = h1;
            } else {
                *(float2*)&Cf[(size_t)row * N + col] = o0;
                *(float2*)&Cf[(size_t)(row + 8) * N + col] = o1;
            }
        }
    }
}

// ---------------------------------------------------------------------------
// Tensor-core flash attention (causal), fp16 mma m16n8k16. (unchanged R11)
// ---------------------------------------------------------------------------
#define KSTR_H 136
#define PSTR_H 136
#define FA_SMEM ((64 * KSTR_H * 2 + 128 * PSTR_H) * 2)   // 69632 bytes

__global__ __launch_bounds__(256) void flash_attn_tc(
    const __half* __restrict__ qkv, __half* __restrict__ Y)
{
    extern __shared__ __half smh[];
    __half* Ks = smh;
    __half* Vs = Ks + 64 * KSTR_H;
    __half* Pw = Vs + 64 * KSTR_H;

    const int tid = threadIdx.x;
    const int wid = tid >> 5;
    const int lid = tid & 31;
    const int g   = lid >> 2;
    const int tg  = lid & 3;
    const int qb  = blockIdx.x;
    const int q0  = qb * 128;
    const int bh  = blockIdx.y;
    const int b   = bh >> 4;
    const int h   = bh & 15;

    const int row0 = q0 + wid * 16 + g;

    const __half* qptr = qkv + ((size_t)(b * Sn + row0)) * TDn + h * DHn;
    uint32_t qf[8][4];
#pragma unroll
    for (int kt = 0; kt < 8; kt++) {
        qf[kt][0] = *(const uint32_t*)(qptr + kt * 16 + 2 * tg);
        qf[kt][1] = *(const uint32_t*)(qptr + (size_t)8 * TDn + kt * 16 + 2 * tg);
        qf[kt][2] = *(const uint32_t*)(qptr + kt * 16 + 8 + 2 * tg);
        qf[kt][3] = *(const uint32_t*)(qptr + (size_t)8 * TDn + kt * 16 + 8 + 2 * tg);
    }

    float ofr[16][4];
#pragma unroll
    for (int nt = 0; nt < 16; nt++)
#pragma unroll
        for (int r = 0; r < 4; r++) ofr[nt][r] = 0.f;

    float m0 = -1e30f, m1 = -1e30f, l0 = 0.f, l1 = 0.f;

    const __half* kbase = qkv + ((size_t)(b * Sn)) * TDn + Dn + h * DHn;
    const __half* vbase = kbase + Dn;
    __half* prow = Pw + (wid * 16) * PSTR_H;

    const int ldi = lid >> 3;
    const int ldj = lid & 7;

    const int nkb = 2 * qb + 2;
    for (int kb = 0; kb < nkb; kb++) {
        __syncthreads();
        const int k0 = kb * 64;

#pragma unroll
        for (int i = 0; i < 4; i++) {
            int idx = tid + i * 256;
            int r  = idx >> 4;
            int s8 = (idx & 15) << 3;
            const size_t go = (size_t)(k0 + r) * TDn + s8;
            *(uint4*)&Ks[r * KSTR_H + s8] = *(const uint4*)(kbase + go);
            *(uint4*)&Vs[r * KSTR_H + s8] = *(const uint4*)(vbase + go);
        }
        __syncthreads();

        float sc[8][4];
#pragma unroll
        for (int nt = 0; nt < 8; nt++)
#pragma unroll
            for (int r = 0; r < 4; r++) sc[nt][r] = 0.f;

#pragma unroll
        for (int kt = 0; kt < 8; kt++) {
#pragma unroll
            for (int nt = 0; nt < 8; nt++) {
                const __half* bp = &Ks[(nt * 8 + g) * KSTR_H + kt * 16 + 2 * tg];
                uint32_t b0 = *(const uint32_t*)bp;
                uint32_t b1 = *(const uint32_t*)(bp + 8);
                mma_f16(sc[nt], qf[kt][0], qf[kt][1], qf[kt][2], qf[kt][3],
                        b0, b1);
            }
        }

        if (kb >= 2 * qb) {
#pragma unroll
            for (int nt = 0; nt < 8; nt++) {
                int col = k0 + nt * 8 + 2 * tg;
                if (col > row0)     sc[nt][0] = -1e30f;
                if (col + 1 > row0) sc[nt][1] = -1e30f;
                if (col > row0 + 8)     sc[nt][2] = -1e30f;
                if (col + 1 > row0 + 8) sc[nt][3] = -1e30f;
            }
        }

        float mx0 = -1e30f, mx1 = -1e30f;
#pragma unroll
        for (int nt = 0; nt < 8; nt++) {
            mx0 = fmaxf(mx0, fmaxf(sc[nt][0], sc[nt][1]));
            mx1 = fmaxf(mx1, fmaxf(sc[nt][2], sc[nt][3]));
        }
        mx0 = fmaxf(mx0, __shfl_xor_sync(0xffffffffu, mx0, 1));
        mx0 = fmaxf(mx0, __shfl_xor_sync(0xffffffffu, mx0, 2));
        mx1 = fmaxf(mx1, __shfl_xor_sync(0xffffffffu, mx1, 1));
        mx1 = fmaxf(mx1, __shfl_xor_sync(0xffffffffu, mx1, 2));

        const float mn0 = fmaxf(m0, mx0);
        const float mn1 = fmaxf(m1, mx1);
        const float a0 = __expf(m0 - mn0);
        const float a1 = __expf(m1 - mn1);
        m0 = mn0; m1 = mn1;

        float s0 = 0.f, s1 = 0.f;
#pragma unroll
        for (int nt = 0; nt < 8; nt++) {
            sc[nt][0] = __expf(sc[nt][0] - mn0);
            sc[nt][1] = __expf(sc[nt][1] - mn0);
            sc[nt][2] = __expf(sc[nt][2] - mn1);
            sc[nt][3] = __expf(sc[nt][3] - mn1);
            s0 += sc[nt][0] + sc[nt][1];
            s1 += sc[nt][2] + sc[nt][3];
        }
        s0 += __shfl_xor_sync(0xffffffffu, s0, 1);
        s0 += __shfl_xor_sync(0xffffffffu, s0, 2);
        s1 += __shfl_xor_sync(0xffffffffu, s1, 1);
        s1 += __shfl_xor_sync(0xffffffffu, s1, 2);
        l0 = l0 * a0 + s0;
        l1 = l1 * a1 + s1;

#pragma unroll
        for (int nt = 0; nt < 16; nt++) {
            ofr[nt][0] *= a0; ofr[nt][1] *= a0;
            ofr[nt][2] *= a1; ofr[nt][3] *= a1;
        }

        __syncwarp();
#pragma unroll
        for (int nt = 0; nt < 8; nt++) {
            const int col = nt * 8 + 2 * tg;
            *(__half2*)&prow[g * PSTR_H + col] =
                __floats2half2_rn(sc[nt][0], sc[nt][1]);
            *(__half2*)&prow[(g + 8) * PSTR_H + col] =
                __floats2half2_rn(sc[nt][2], sc[nt][3]);
        }
        __syncwarp();

#pragma unroll
        for (int kt = 0; kt < 4; kt++) {
            uint32_t pa0 = *(const uint32_t*)&prow[g * PSTR_H + kt * 16 + 2 * tg];
            uint32_t pa1 = *(const uint32_t*)&prow[(g + 8) * PSTR_H + kt * 16 + 2 * tg];
            uint32_t pa2 = *(const uint32_t*)&prow[g * PSTR_H + kt * 16 + 8 + 2 * tg];
            uint32_t pa3 = *(const uint32_t*)&prow[(g + 8) * PSTR_H + kt * 16 + 8 + 2 * tg];
            const int vrow = kt * 16 + (ldi & 1) * 8 + ldj;
#pragma unroll
            for (int ntp = 0; ntp < 8; ntp++) {
                uint32_t r0, r1, r2, r3;
                ldsm4t(r0, r1, r2, r3,
                       &Vs[vrow * KSTR_H + ntp * 16 + (ldi >> 1) * 8]);
                mma_f16(ofr[2 * ntp],     pa0, pa1, pa2, pa3, r0, r1);
                mma_f16(ofr[2 * ntp + 1], pa0, pa1, pa2, pa3, r2, r3);
            }
        }
    }

    const float inv0 = 1.0f / l0;
    const float inv1 = 1.0f / l1;
    __half* yrow = Y + ((size_t)(b * Sn + row0)) * Dn + h * DHn;
#pragma unroll
    for (int nt = 0; nt < 16; nt++) {
        const int col = nt * 8 + 2 * tg;
        __half2 h0 = __floats2half2_rn(ofr[nt][0] * inv0, ofr[nt][1] * inv0);
        __half2 h1 = __floats2half2_rn(ofr[nt][2] * inv1, ofr[nt][3] * inv1);
        *(__half2*)&yrow[col] = h0;
        *(__half2*)&yrow[(size_t)8 * Dn + col] = h1;
    }
}

// ---------------------------------------------------------------------------
extern "C" void kernel_launch(void* const* d_in, const int* in_sizes, int n_in,
                              void* d_out, int out_size)
{
    (void)in_sizes; (void)n_in; (void)out_size;
    const float* x      = (const float*)d_in[0];
    const float* qkv_w  = (const float*)d_in[1];
    const float* qkv_b  = (const float*)d_in[2];
    const float* out_w  = (const float*)d_in[3];
    const float* out_b  = (const float*)d_in[4];
    float* out = (float*)d_out;

    __half *qkv, *y, *xt, *wq, *wo;
    cudaGetSymbolAddress((void**)&qkv, g_qkv);
    cudaGetSymbolAddress((void**)&y, g_y);
    cudaGetSymbolAddress((void**)&xt, g_xt);
    cudaGetSymbolAddress((void**)&wq, g_wq);
    cudaGetSymbolAddress((void**)&wo, g_wo);

    cudaFuncSetAttribute(mma_gemm_h,
                         cudaFuncAttributeMaxDynamicSharedMemorySize, GEMM2_SMEM);
    cudaFuncSetAttribute(flash_attn_tc,
                         cudaFuncAttributeMaxDynamicSharedMemorySize, FA_SMEM);

    // 0) Pre-convert inputs to fp16
    {
        int n8x = (NROWS * Dn) / 8;
        conv_h_kernel<<<(n8x + 255) / 256, 256>>>(x, xt, n8x);
        int n8q = (TDn * Dn) / 8;
        conv_h_kernel<<<(n8q + 255) / 256, 256>>>(qkv_w, wq, n8q);
        int n8o = (Dn * Dn) / 8;
        conv_h_kernel<<<(n8o + 255) / 256, 256>>>(out_w, wo, n8o);
    }

    // 1) QKV projection + fused RoPE + q-scale, half output
    {
        dim3 grid(TDn / 128, NROWS / 128);
        mma_gemm_h<<<grid, 256, GEMM2_SMEM>>>(xt, wq, qkv_b, nullptr, qkv,
                                              NROWS, TDn, Dn, 1);
    }

    // 2) Flash attention (fp16 mma), emits half y
    {
        dim3 grid(Sn / 128, Bn * Hn);
        flash_attn_tc<<<grid, 256, FA_SMEM>>>(qkv, y);
    }

    // 3) Output projection (fp16 mma, fp32 output)
    {
        dim3 grid(Dn / 128, NROWS / 128);
        mma_gemm_h<<<grid, 256, GEMM2_SMEM>>>(y, wo, out_b, out, nullptr,
                                              NROWS, Dn, Dn, 0);
    }
}